// round 12
// baseline (speedup 1.0000x reference)
#include <cuda_runtime.h>
#include <cuda_bf16.h>
#include <math.h>

#define NN 20000
#define EE 200000
#define ND 64
#define ED 32
#define GD 32
#define HD 128
#define DOF 6
#define PI_F 3.14159265358979f

#define EPB 32     // edges per edge-block
#define RPB 64     // rows per edge-block
#define TPB 256    // threads per block (both kernels)

// A tiles: pitch 200 els = 400 B (== 16 mod 128 -> ldmatrix conflict-free)
#define SP   200
#define SPB  400
#define EAIMG (RPB * SPB)     // 25600 B per A image
// streamed W chunk: 128 N-rows x 32 K-els, row pitch 80 B
#define ECH_P   80
#define ECH_IMG 10240
#define ECH_ELS 5120
// edge smem layout: [Ah][Al][B0h][B0l][B1h][B1l]
#define EBB   (2 * EAIMG)         // 51200, chunk-buffer base
#define ESMEM (EBB + 4 * ECH_IMG) // 92160

// node tiles: pitch 264 els = 528 B, K up to 224
#define SP2   264
#define SPB2  528
#define NAIMG (64 * SPB2)         // 33792
#define NBB   (2 * NAIMG)         // 67584, chunk-buffer base
#define NSMEM (NBB + 4 * ECH_IMG) // 108544  -> 2 blocks/SM

// chunked weight images
static __device__ __align__(16) __nv_bfloat16 gW1ch[6 * ECH_ELS];
static __device__ __align__(16) __nv_bfloat16 gW1cl[6 * ECH_ELS];
static __device__ __align__(16) __nv_bfloat16 gW2ch[4 * ECH_ELS];
static __device__ __align__(16) __nv_bfloat16 gW2cl[4 * ECH_ELS];
static __device__ __align__(16) __nv_bfloat16 gW3ch[7 * ECH_ELS];
static __device__ __align__(16) __nv_bfloat16 gW3cl[7 * ECH_ELS];
static __device__ __align__(16) __nv_bfloat16 gW4ch[4 * ECH_ELS];
static __device__ __align__(16) __nv_bfloat16 gW4cl[4 * ECH_ELS];

__device__ float g_sums[NN * HD];
__device__ float g_cnt[NN];

__device__ __forceinline__ unsigned smem_u32(const void* p) {
    unsigned a;
    asm("{ .reg .u64 t; cvta.to.shared.u64 t, %1; cvt.u32.u64 %0, t; }" : "=r"(a) : "l"(p));
    return a;
}
__device__ __forceinline__ void split2(float a, float b, unsigned& hi, unsigned& lo) {
    __nv_bfloat16 ha = __float2bfloat16(a), hb = __float2bfloat16(b);
    __nv_bfloat162 th; th.x = ha; th.y = hb;
    hi = *(unsigned*)&th;
    __nv_bfloat162 tl;
    tl.x = __float2bfloat16(a - __bfloat162float(ha));
    tl.y = __float2bfloat16(b - __bfloat162float(hb));
    lo = *(unsigned*)&tl;
}
__device__ __forceinline__ void split4v(float4 v, uint2& hi, uint2& lo) {
    unsigned h0, l0, h1, l1;
    split2(v.x, v.y, h0, l0);
    split2(v.z, v.w, h1, l1);
    hi = make_uint2(h0, h1);
    lo = make_uint2(l0, l1);
}
__device__ __forceinline__ unsigned eoff(int r, int k)  { return (unsigned)(r * SPB  + k * 2); }
__device__ __forceinline__ unsigned eoff2(int r, int k) { return (unsigned)(r * SPB2 + k * 2); }

__device__ __forceinline__ void ldm4(unsigned addr, unsigned* r) {
    asm volatile("ldmatrix.sync.aligned.m8n8.x4.shared.b16 {%0,%1,%2,%3}, [%4];"
        : "=r"(r[0]), "=r"(r[1]), "=r"(r[2]), "=r"(r[3]) : "r"(addr));
}
__device__ __forceinline__ void mma16816(float* d, const unsigned* a, unsigned b0, unsigned b1) {
    asm volatile("mma.sync.aligned.m16n8k16.row.col.f32.bf16.bf16.f32 "
        "{%0,%1,%2,%3}, {%4,%5,%6,%7}, {%8,%9}, {%0,%1,%2,%3};"
        : "+f"(d[0]), "+f"(d[1]), "+f"(d[2]), "+f"(d[3])
        : "r"(a[0]), "r"(a[1]), "r"(a[2]), "r"(a[3]), "r"(b0), "r"(b1));
}

// ---- streamed-chunk helpers ----
__device__ __forceinline__ void ldg_chunk(const uint2* gh, const uint2* gl, int c, int tid,
                                          uint2 rh[5], uint2 rl[5]) {
    const uint2* ph = gh + c * (ECH_IMG / 8) + tid;
    const uint2* pl = gl + c * (ECH_IMG / 8) + tid;
    #pragma unroll
    for (int i = 0; i < 5; i++) { rh[i] = ph[i * 256]; rl[i] = pl[i * 256]; }
}
__device__ __forceinline__ void sts_chunk(char* bh, char* bl, int tid,
                                          const uint2 rh[5], const uint2 rl[5]) {
    uint2* dh = (uint2*)bh + tid;
    uint2* dl = (uint2*)bl + tid;
    #pragma unroll
    for (int i = 0; i < 5; i++) { dh[i * 256] = rh[i]; dl[i * 256] = rl[i]; }
}

// 3-term MMA over one K32 chunk (warp tile 32x32); APITCH = A row pitch bytes
template<int APITCH>
__device__ __forceinline__ void mma_chunk(unsigned aH, unsigned aL, unsigned bH, unsigned bL,
                                          unsigned aoffc, unsigned boff0, int steps,
                                          float d[2][4][4]) {
    for (int s = 0; s < steps; s++) {
        unsigned ka = aoffc + (unsigned)s * 32u;
        unsigned kb = boff0 + (unsigned)s * 32u;
        unsigned ah0[4], ah1[4], al0[4], al1[4];
        unsigned bh0[4], bh1[4], bl0[4], bl1[4];
        ldm4(aH + ka, ah0);
        ldm4(aH + ka + 16u * APITCH, ah1);
        ldm4(aL + ka, al0);
        ldm4(aL + ka + 16u * APITCH, al1);
        ldm4(bH + kb, bh0);
        ldm4(bH + kb + 16u * ECH_P, bh1);
        ldm4(bL + kb, bl0);
        ldm4(bL + kb + 16u * ECH_P, bl1);
        mma16816(d[0][0], ah0, bh0[0], bh0[1]);
        mma16816(d[0][1], ah0, bh0[2], bh0[3]);
        mma16816(d[0][2], ah0, bh1[0], bh1[1]);
        mma16816(d[0][3], ah0, bh1[2], bh1[3]);
        mma16816(d[1][0], ah1, bh0[0], bh0[1]);
        mma16816(d[1][1], ah1, bh0[2], bh0[3]);
        mma16816(d[1][2], ah1, bh1[0], bh1[1]);
        mma16816(d[1][3], ah1, bh1[2], bh1[3]);
        mma16816(d[0][0], al0, bh0[0], bh0[1]);
        mma16816(d[0][1], al0, bh0[2], bh0[3]);
        mma16816(d[0][2], al0, bh1[0], bh1[1]);
        mma16816(d[0][3], al0, bh1[2], bh1[3]);
        mma16816(d[1][0], al1, bh0[0], bh0[1]);
        mma16816(d[1][1], al1, bh0[2], bh0[3]);
        mma16816(d[1][2], al1, bh1[0], bh1[1]);
        mma16816(d[1][3], al1, bh1[2], bh1[3]);
        mma16816(d[0][0], ah0, bl0[0], bl0[1]);
        mma16816(d[0][1], ah0, bl0[2], bl0[3]);
        mma16816(d[0][2], ah0, bl1[0], bl1[1]);
        mma16816(d[0][3], ah0, bl1[2], bl1[3]);
        mma16816(d[1][0], ah1, bl0[0], bl0[1]);
        mma16816(d[1][1], ah1, bl0[2], bl0[3]);
        mma16816(d[1][2], ah1, bl1[0], bl1[1]);
        mma16816(d[1][3], ah1, bl1[2], bl1[3]);
    }
}

// double-buffered streamed GEMM: NCH chunks, last chunk has LAST k16-steps.
// A hi at smraw+0, A lo at smraw+ALOFF, chunk buffers at smraw+BBASE.
template<int NCH, int LAST, int APITCH, int ALOFF, int BBASE>
__device__ __forceinline__ void gemm_stream(const __nv_bfloat16* gWh, const __nv_bfloat16* gWl,
                                            char* smraw, unsigned sb,
                                            unsigned aoff0, unsigned boff0, int tid,
                                            float d[2][4][4]) {
    const uint2* gh = (const uint2*)gWh;
    const uint2* gl = (const uint2*)gWl;
    uint2 rh[5], rl[5];
    ldg_chunk(gh, gl, 0, tid, rh, rl);
    sts_chunk(smraw + BBASE, smraw + BBASE + ECH_IMG, tid, rh, rl);
    if (NCH > 1) ldg_chunk(gh, gl, 1, tid, rh, rl);
    __syncthreads();
    #pragma unroll
    for (int c = 0; c < NCH; c++) {
        unsigned bH = sb + BBASE + (unsigned)((c & 1) ? 2 * ECH_IMG : 0);
        unsigned bL = bH + ECH_IMG;
        int steps = (c == NCH - 1) ? LAST : 2;
        mma_chunk<APITCH>(sb, sb + ALOFF, bH, bL, aoff0 + (unsigned)c * 64u, boff0, steps, d);
        if (c + 1 < NCH)
            sts_chunk(smraw + BBASE + (((c + 1) & 1) ? 2 * ECH_IMG : 0),
                      smraw + BBASE + (((c + 1) & 1) ? 2 * ECH_IMG : 0) + ECH_IMG, tid, rh, rl);
        if (c + 2 < NCH) ldg_chunk(gh, gl, c + 2, tid, rh, rl);
        __syncthreads();
    }
}

// ---- init: zero accumulators + build all chunked weight images ----
__global__ void init_kernel(const float* __restrict__ W1, const float* __restrict__ W2,
                            const float* __restrict__ W3, const float* __restrict__ W4) {
    int idx = blockIdx.x * blockDim.x + threadIdx.x;
    if (idx < NN * HD / 4) ((float4*)g_sums)[idx] = make_float4(0.f, 0.f, 0.f, 0.f);
    if (idx < NN)          g_cnt[idx] = 0.0f;

    const int NW1 = 6 * ECH_ELS, NW2 = 4 * ECH_ELS, NW3 = 7 * ECH_ELS, NW4 = 4 * ECH_ELS;
    if (idx < NW1) {
        int c = idx / ECH_ELS, rem = idx % ECH_ELS;
        int n = rem / 40, kk = rem % 40;
        int k = c * 32 + kk;
        float w = (kk < 32 && k < 172) ? W1[k * HD + n] : 0.f;
        __nv_bfloat16 h = __float2bfloat16(w);
        __nv_bfloat16 l = __float2bfloat16(w - __bfloat162float(h));
        gW1ch[idx] = h; gW1cl[idx] = l;
    } else if (idx < NW1 + NW2) {
        int j = idx - NW1;
        int c = j / ECH_ELS, rem = j % ECH_ELS;
        int n = rem / 40, kk = rem % 40;
        int k = c * 32 + kk;
        float w = (kk < 32) ? W2[k * HD + n] : 0.f;
        __nv_bfloat16 h = __float2bfloat16(w);
        __nv_bfloat16 l = __float2bfloat16(w - __bfloat162float(h));
        gW2ch[j] = h; gW2cl[j] = l;
    } else if (idx < NW1 + NW2 + NW3) {
        int j = idx - (NW1 + NW2);
        int c = j / ECH_ELS, rem = j % ECH_ELS;
        int n = rem / 40, kk = rem % 40;
        int k = c * 32 + kk;
        float w = (kk < 32) ? W3[k * HD + n] : 0.f;   // K=224 = 7*32 exact
        __nv_bfloat16 h = __float2bfloat16(w);
        __nv_bfloat16 l = __float2bfloat16(w - __bfloat162float(h));
        gW3ch[j] = h; gW3cl[j] = l;
    } else if (idx < NW1 + NW2 + NW3 + NW4) {
        int j = idx - (NW1 + NW2 + NW3);
        int c = j / ECH_ELS, rem = j % ECH_ELS;
        int n = rem / 40, kk = rem % 40;
        int k = c * 32 + kk;
        float w = (kk < 32 && n < ND + DOF) ? W4[k * (ND + DOF) + n] : 0.f;
        __nv_bfloat16 h = __float2bfloat16(w);
        __nv_bfloat16 l = __float2bfloat16(w - __bfloat162float(h));
        gW4ch[j] = h; gW4cl[j] = l;
    }
}

// ---------------- Edge kernel: 32 edges, streamed W, 2 blocks/SM ----------------
__global__ __launch_bounds__(TPB, 2)
void edge_kernel(const float* __restrict__ xfeat, const float* __restrict__ T_R,
                 const float* __restrict__ T_t,  const float* __restrict__ edge_feat,
                 const float* __restrict__ TijR, const float* __restrict__ Tijt,
                 const int* __restrict__ ei,
                 const float* __restrict__ b1, const float* __restrict__ b2)
{
    extern __shared__ __align__(16) char smraw[];
    char* sAh = smraw;
    char* sAl = smraw + EAIMG;
    unsigned sb = smem_u32(smraw);

    __shared__ int sNode[RPB];
    __shared__ float sBias1[HD], sBias2[HD];

    int tid = threadIdx.x;
    int warp = tid >> 5, lane = tid & 31;
    int e0 = blockIdx.x * EPB;

    if (tid < HD)          sBias1[tid] = b1[tid];
    else if (tid < 2 * HD) sBias2[tid - HD] = b2[tid - HD];

    {
        int sub = tid & 7;
        int el  = tid >> 3;
        int e   = e0 + el;
        int vi = ei[e], vj = ei[EE + e];
        const float4* xi4 = (const float4*)(xfeat + vi * ND);
        const float4* xj4 = (const float4*)(xfeat + vj * ND);
        const float4* ef4 = (const float4*)(edge_feat + e * ED);
        int rA = el, rB = EPB + el;
        #pragma unroll
        for (int q = sub; q < 16; q += 8) {
            uint2 hi, lo;
            split4v(xi4[q], hi, lo);
            unsigned o1 = eoff(rA, 4 * q), o2 = eoff(rB, 64 + 4 * q);
            *(uint2*)(sAh + o1) = hi; *(uint2*)(sAl + o1) = lo;
            *(uint2*)(sAh + o2) = hi; *(uint2*)(sAl + o2) = lo;
            split4v(xj4[q], hi, lo);
            o1 = eoff(rA, 64 + 4 * q); o2 = eoff(rB, 4 * q);
            *(uint2*)(sAh + o1) = hi; *(uint2*)(sAl + o1) = lo;
            *(uint2*)(sAh + o2) = hi; *(uint2*)(sAl + o2) = lo;
        }
        uint2 hi, lo;
        split4v(ef4[sub], hi, lo);
        unsigned o1 = eoff(rA, 128 + 4 * sub), o2 = eoff(rB, 128 + 4 * sub);
        *(uint2*)(sAh + o1) = hi; *(uint2*)(sAl + o1) = lo;
        *(uint2*)(sAh + o2) = hi; *(uint2*)(sAl + o2) = lo;
    }

    if (tid < EPB) {
        int e = e0 + tid;
        int vi = ei[e], vj = ei[EE + e];
        sNode[tid]       = vj;
        sNode[EPB + tid] = vi;
        float Ri[9], Rj[9], Tr[9], ti[3], tj[3], tt[3];
        #pragma unroll
        for (int k = 0; k < 9; k++) { Ri[k] = T_R[vi*9+k]; Rj[k] = T_R[vj*9+k]; Tr[k] = TijR[e*9+k]; }
        #pragma unroll
        for (int k = 0; k < 3; k++) { ti[k] = T_t[vi*3+k]; tj[k] = T_t[vj*3+k]; tt[k] = Tijt[e*3+k]; }
        float A[9], ta[3];
        #pragma unroll
        for (int r = 0; r < 3; r++)
            #pragma unroll
            for (int c = 0; c < 3; c++)
                A[r*3+c] = Rj[r*3+0]*Ri[c*3+0] + Rj[r*3+1]*Ri[c*3+1] + Rj[r*3+2]*Ri[c*3+2];
        #pragma unroll
        for (int r = 0; r < 3; r++)
            ta[r] = tj[r] - (A[r*3+0]*ti[0] + A[r*3+1]*ti[1] + A[r*3+2]*ti[2]);
        float arrA[12], arrB[12];
        {
            float Re[9], te[3];
            #pragma unroll
            for (int r = 0; r < 3; r++)
                #pragma unroll
                for (int c = 0; c < 3; c++)
                    Re[r*3+c] = A[r*3+0]*Tr[c*3+0] + A[r*3+1]*Tr[c*3+1] + A[r*3+2]*Tr[c*3+2];
            #pragma unroll
            for (int r = 0; r < 3; r++)
                te[r] = ta[r] - (Re[r*3+0]*tt[0] + Re[r*3+1]*tt[1] + Re[r*3+2]*tt[2]);
            arrA[0]=Re[0]; arrA[1]=Re[1]; arrA[2]=Re[2];  arrA[3]=te[0];
            arrA[4]=Re[3]; arrA[5]=Re[4]; arrA[6]=Re[5];  arrA[7]=te[1];
            arrA[8]=Re[6]; arrA[9]=Re[7]; arrA[10]=Re[8]; arrA[11]=te[2];
        }
        {
            float tb[3], Rf[9], tf[3];
            #pragma unroll
            for (int r = 0; r < 3; r++)
                tb[r] = ti[r] - (A[0+r]*tj[0] + A[3+r]*tj[1] + A[6+r]*tj[2]);
            #pragma unroll
            for (int r = 0; r < 3; r++)
                #pragma unroll
                for (int c = 0; c < 3; c++)
                    Rf[r*3+c] = A[0+r]*Tr[0+c] + A[3+r]*Tr[3+c] + A[6+r]*Tr[6+c];
            #pragma unroll
            for (int r = 0; r < 3; r++)
                tf[r] = tb[r] + (A[0+r]*tt[0] + A[3+r]*tt[1] + A[6+r]*tt[2]);
            arrB[0]=Rf[0]; arrB[1]=Rf[1]; arrB[2]=Rf[2];  arrB[3]=tf[0];
            arrB[4]=Rf[3]; arrB[5]=Rf[4]; arrB[6]=Rf[5];  arrB[7]=tf[1];
            arrB[8]=Rf[6]; arrB[9]=Rf[7]; arrB[10]=Rf[8]; arrB[11]=tf[2];
        }
        #pragma unroll
        for (int half = 0; half < 2; half++) {
            int r = half ? (EPB + tid) : tid;
            const float* arr = half ? arrB : arrA;
            #pragma unroll
            for (int m = 0; m < 6; m++) {
                unsigned hi, lo;
                split2(arr[2*m], arr[2*m+1], hi, lo);
                unsigned o = eoff(r, 160 + 2 * m);
                *(unsigned*)(sAh + o) = hi; *(unsigned*)(sAl + o) = lo;
            }
            #pragma unroll
            for (int k = 172; k < 176; k += 2) {
                unsigned o = eoff(r, k);
                *(unsigned*)(sAh + o) = 0u; *(unsigned*)(sAl + o) = 0u;
            }
        }
    }
    // gemm_stream's first __syncthreads orders the build before MMA.

    const int m_base = (warp & 1) * 32;
    const int n_base = (warp >> 1) * 32;
    unsigned aoff0 = (unsigned)((m_base + (lane & 15)) * SPB + (lane >> 4) * 16);
    unsigned boff0 = (unsigned)((n_base + (lane & 7) + ((lane >> 4) & 1) * 8) * ECH_P
                                + ((lane >> 3) & 1) * 16);

    float d[2][4][4];
    #pragma unroll
    for (int i = 0; i < 2; i++)
        #pragma unroll
        for (int j = 0; j < 4; j++)
            #pragma unroll
            for (int c = 0; c < 4; c++) d[i][j][c] = 0.f;

    gemm_stream<6, 1, SPB, EAIMG, EBB>(gW1ch, gW1cl, smraw, sb, aoff0, boff0, tid, d);

    {
        int r0b = m_base + (lane >> 2);
        int colb = n_base + 2 * (lane & 3);
        #pragma unroll
        for (int mi = 0; mi < 2; mi++) {
            #pragma unroll
            for (int nb = 0; nb < 4; nb++) {
                int col = colb + nb * 8;
                float bx = sBias1[col], by = sBias1[col + 1];
                int r0 = r0b + mi * 16, r1 = r0 + 8;
                unsigned hi, lo;
                split2(fmaxf(d[mi][nb][0] + bx, 0.f), fmaxf(d[mi][nb][1] + by, 0.f), hi, lo);
                unsigned o = eoff(r0, col);
                *(unsigned*)(sAh + o) = hi; *(unsigned*)(sAl + o) = lo;
                split2(fmaxf(d[mi][nb][2] + bx, 0.f), fmaxf(d[mi][nb][3] + by, 0.f), hi, lo);
                o = eoff(r1, col);
                *(unsigned*)(sAh + o) = hi; *(unsigned*)(sAl + o) = lo;
            }
        }
    }
    __syncthreads();

    #pragma unroll
    for (int i = 0; i < 2; i++)
        #pragma unroll
        for (int j = 0; j < 4; j++)
            #pragma unroll
            for (int c = 0; c < 4; c++) d[i][j][c] = 0.f;

    gemm_stream<4, 2, SPB, EAIMG, EBB>(gW2ch, gW2cl, smraw, sb, aoff0, boff0, tid, d);

    {
        int r0b = m_base + (lane >> 2);
        int colb = n_base + 2 * (lane & 3);
        #pragma unroll
        for (int mi = 0; mi < 2; mi++) {
            int r0 = r0b + mi * 16, r1 = r0 + 8;
            int node0 = sNode[r0], node1 = sNode[r1];
            #pragma unroll
            for (int nb = 0; nb < 4; nb++) {
                int col = colb + nb * 8;
                float bx = sBias2[col], by = sBias2[col + 1];
                float v0 = fmaxf(d[mi][nb][0] + bx, 0.f);
                float v1 = fmaxf(d[mi][nb][1] + by, 0.f);
                float v2 = fmaxf(d[mi][nb][2] + bx, 0.f);
                float v3 = fmaxf(d[mi][nb][3] + by, 0.f);
                float* p0 = g_sums + (size_t)node0 * HD + col;
                float* p1 = g_sums + (size_t)node1 * HD + col;
                asm volatile("red.global.add.v2.f32 [%0], {%1, %2};"
                             :: "l"(p0), "f"(v0), "f"(v1) : "memory");
                asm volatile("red.global.add.v2.f32 [%0], {%1, %2};"
                             :: "l"(p1), "f"(v2), "f"(v3) : "memory");
            }
        }
        if ((warp >> 1) == 0 && (lane & 3) == 0) {
            int rr = lane >> 2;
            atomicAdd(g_cnt + sNode[m_base + rr],      1.0f);
            atomicAdd(g_cnt + sNode[m_base + rr + 8],  1.0f);
            atomicAdd(g_cnt + sNode[m_base + rr + 16], 1.0f);
            atomicAdd(g_cnt + sNode[m_base + rr + 24], 1.0f);
        }
    }
}

// ---------------- Node kernel: streamed W, 2 blocks/SM ----------------
__global__ __launch_bounds__(TPB, 2)
void node_kernel(const float* __restrict__ xfeat, const float* __restrict__ T_R,
                 const float* __restrict__ T_t,  const float* __restrict__ u,
                 const int* __restrict__ batch,
                 const float* __restrict__ b3, const float* __restrict__ b4,
                 float* __restrict__ out)
{
    extern __shared__ __align__(16) char smraw[];
    char* sAh = smraw;
    char* sAl = smraw + NAIMG;
    unsigned sb = smem_u32(smraw);

    __shared__ float sBias3[HD], sBias4[ND + DOF];
    __shared__ float sInv[64];
    __shared__ float sPose[64 * DOF];

    int tid = threadIdx.x;
    int warp = tid >> 5, lane = tid & 31;
    int n0 = blockIdx.x * 64;

    if (tid < HD)                 sBias3[tid] = b3[tid];
    else if (tid < HD + ND + DOF) sBias4[tid - HD] = b4[tid - HD];
    if (tid < 64) {
        int n = n0 + tid;
        sInv[tid] = (n < NN) ? 1.0f / fmaxf(g_cnt[n], 1.0f) : 0.f;
    }
    __syncthreads();   // sInv before build

    // ---- build g = [aggr | xfeat | u[batch]] as bf16 hi/lo ----
    for (int idx = tid; idx < 64 * 112; idx += TPB) {
        int r = idx / 112;
        int k = 2 * (idx % 112);
        int n = n0 + r;
        float v0 = 0.f, v1 = 0.f;
        if (n < NN) {
            if (k < HD) {
                float iv = sInv[r];
                v0 = g_sums[(size_t)n * HD + k] * iv;
                v1 = g_sums[(size_t)n * HD + k + 1] * iv;
            } else if (k < HD + ND) {
                v0 = xfeat[(size_t)n * ND + k - HD];
                v1 = xfeat[(size_t)n * ND + k - HD + 1];
            } else {
                int bb = batch[n];
                v0 = u[bb * GD + k - HD - ND];
                v1 = u[bb * GD + k - HD - ND + 1];
            }
        }
        unsigned hi, lo;
        split2(v0, v1, hi, lo);
        unsigned o = eoff2(r, k);
        *(unsigned*)(sAh + o) = hi;
        *(unsigned*)(sAl + o) = lo;
    }
    // gemm_stream's first sync orders build before MMA.

    const int m_base = (warp & 1) * 32;
    const int n_base = (warp >> 1) * 32;
    unsigned aoff0 = (unsigned)((m_base + (lane & 15)) * SPB2 + (lane >> 4) * 16);
    unsigned boff0 = (unsigned)((n_base + (lane & 7) + ((lane >> 4) & 1) * 8) * ECH_P
                                + ((lane >> 3) & 1) * 16);

    float d[2][4][4];
    #pragma unroll
    for (int i = 0; i < 2; i++)
        #pragma unroll
        for (int j = 0; j < 4; j++)
            #pragma unroll
            for (int c = 0; c < 4; c++) d[i][j][c] = 0.f;

    // GEMM3: K=224 = 7 chunks
    gemm_stream<7, 2, SPB2, NAIMG, NBB>(gW3ch, gW3cl, smraw, sb, aoff0, boff0, tid, d);

    // epilogue3: bias+relu -> hidden bf16 hi/lo into A region
    {
        int r0b = m_base + (lane >> 2);
        int colb = n_base + 2 * (lane & 3);
        #pragma unroll
        for (int mi = 0; mi < 2; mi++) {
            #pragma unroll
            for (int nb = 0; nb < 4; nb++) {
                int col = colb + nb * 8;
                float bx = sBias3[col], by = sBias3[col + 1];
                int r0 = r0b + mi * 16, r1 = r0 + 8;
                unsigned hi, lo;
                split2(fmaxf(d[mi][nb][0] + bx, 0.f), fmaxf(d[mi][nb][1] + by, 0.f), hi, lo);
                unsigned o = eoff2(r0, col);
                *(unsigned*)(sAh + o) = hi; *(unsigned*)(sAl + o) = lo;
                split2(fmaxf(d[mi][nb][2] + bx, 0.f), fmaxf(d[mi][nb][3] + by, 0.f), hi, lo);
                o = eoff2(r1, col);
                *(unsigned*)(sAh + o) = hi; *(unsigned*)(sAl + o) = lo;
            }
        }
    }
    __syncthreads();

    #pragma unroll
    for (int i = 0; i < 2; i++)
        #pragma unroll
        for (int j = 0; j < 4; j++)
            #pragma unroll
            for (int c = 0; c < 4; c++) d[i][j][c] = 0.f;

    // GEMM4: K=128 = 4 chunks (N cols >= 70 are zero-padded weights)
    gemm_stream<4, 2, SPB2, NAIMG, NBB>(gW4ch, gW4cl, smraw, sb, aoff0, boff0, tid, d);

    // epilogue4: xupd + pose
    {
        int r0b = m_base + (lane >> 2);
        int colb = n_base + 2 * (lane & 3);
        #pragma unroll
        for (int mi = 0; mi < 2; mi++) {
            #pragma unroll
            for (int rr = 0; rr < 2; rr++) {
                int r = r0b + mi * 16 + rr * 8;
                int n = n0 + r;
                #pragma unroll
                for (int nb = 0; nb < 4; nb++) {
                    int col = colb + nb * 8;
                    float v0 = d[mi][nb][rr * 2 + 0];
                    float v1 = d[mi][nb][rr * 2 + 1];
                    if (col < ND) {
                        if (n < NN) {
                            out[(size_t)n * 77 + col]     = xfeat[(size_t)n * ND + col]     + v0 + sBias4[col];
                            out[(size_t)n * 77 + col + 1] = xfeat[(size_t)n * ND + col + 1] + v1 + sBias4[col + 1];
                        }
                    } else if (col < ND + DOF) {
                        sPose[r * DOF + (col - ND)] = v0 + sBias4[col];
                        if (col + 1 < ND + DOF)
                            sPose[r * DOF + (col - ND) + 1] = v1 + sBias4[col + 1];
                    }
                }
            }
        }
    }
    __syncthreads();

    // SE3 epilogue
    if (tid < 64) {
        int n = n0 + tid;
        if (n < NN) {
            float r0 = sPose[tid*6+0], r1 = sPose[tid*6+1], r2 = sPose[tid*6+2];
            float px = sPose[tid*6+3], py = sPose[tid*6+4], pz = sPose[tid*6+5];
            float nr = sqrtf(px*px + py*py + pz*pz);
            float sc = PI_F * tanhf(nr / PI_F) / (nr + 1e-8f);
            px *= sc; py *= sc; pz *= sc;
            float pp = px*px + py*py + pz*pz;
            float th = sqrtf(pp + 1e-12f);
            float a, b, c;
            if (th < 1e-4f) {
                a = 1.f - pp/6.f; b = 0.5f - pp/24.f; c = 1.f/6.f - pp/120.f;
            } else {
                float s = sinf(th), co = cosf(th);
                a = s / th; b = (1.f - co) / pp; c = (th - s) / (pp * th);
            }
            float Km[9] = {0.f,-pz,py,  pz,0.f,-px,  -py,px,0.f};
            float KK[9] = {px*px-pp, px*py,    px*pz,
                           py*px,    py*py-pp, py*pz,
                           pz*px,    pz*py,    pz*pz-pp};
            float Rd[9], V[9];
            #pragma unroll
            for (int q = 0; q < 9; q++) { Rd[q] = a*Km[q] + b*KK[q]; V[q] = b*Km[q] + c*KK[q]; }
            Rd[0] += 1.f; Rd[4] += 1.f; Rd[8] += 1.f;
            V[0]  += 1.f; V[4]  += 1.f; V[8]  += 1.f;
            float td0 = V[0]*r0 + V[1]*r1 + V[2]*r2;
            float td1 = V[3]*r0 + V[4]*r1 + V[5]*r2;
            float td2 = V[6]*r0 + V[7]*r1 + V[8]*r2;
            float TR[9], Tt[3];
            #pragma unroll
            for (int q = 0; q < 9; q++) TR[q] = T_R[n*9+q];
            #pragma unroll
            for (int q = 0; q < 3; q++) Tt[q] = T_t[n*3+q];
            float* o = out + (size_t)n * 77;
            #pragma unroll
            for (int rr = 0; rr < 3; rr++) {
                #pragma unroll
                for (int cc = 0; cc < 3; cc++) {
                    o[64 + rr*3 + cc] = Rd[rr*3+0]*TR[0+cc] + Rd[rr*3+1]*TR[3+cc] + Rd[rr*3+2]*TR[6+cc];
                }
                o[73 + rr] = Rd[rr*3+0]*Tt[0] + Rd[rr*3+1]*Tt[1] + Rd[rr*3+2]*Tt[2]
                           + (rr == 0 ? td0 : (rr == 1 ? td1 : td2));
            }
            o[76] = sqrtf(pp);
        }
    }
}

extern "C" void kernel_launch(void* const* d_in, const int* in_sizes, int n_in,
                              void* d_out, int out_size) {
    const float* xfeat     = (const float*)d_in[0];
    const float* T_R       = (const float*)d_in[1];
    const float* T_t       = (const float*)d_in[2];
    const float* edge_feat = (const float*)d_in[3];
    const float* TijR      = (const float*)d_in[4];
    const float* Tijt      = (const float*)d_in[5];
    const float* u         = (const float*)d_in[6];
    const int*   ei        = (const int*)d_in[7];
    const int*   batch     = (const int*)d_in[8];
    const float* W1 = (const float*)d_in[9];
    const float* b1 = (const float*)d_in[10];
    const float* W2 = (const float*)d_in[11];
    const float* b2 = (const float*)d_in[12];
    const float* W3 = (const float*)d_in[13];
    const float* b3 = (const float*)d_in[14];
    const float* W4 = (const float*)d_in[15];
    const float* b4 = (const float*)d_in[16];
    float* out = (float*)d_out;

    cudaFuncSetAttribute(edge_kernel, cudaFuncAttributeMaxDynamicSharedMemorySize, ESMEM);
    cudaFuncSetAttribute(node_kernel, cudaFuncAttributeMaxDynamicSharedMemorySize, NSMEM);

    init_kernel<<<(NN * HD / 4 + 255) / 256, 256>>>(W1, W2, W3, W4);
    edge_kernel<<<EE / EPB, TPB, ESMEM>>>(xfeat, T_R, T_t, edge_feat, TijR, Tijt,
                                          ei, b1, b2);
    node_kernel<<<(NN + 63) / 64, TPB, NSMEM>>>(xfeat, T_R, T_t, u, batch,
                                                b3, b4, out);
}

// round 16
// speedup vs baseline: 1.5229x; 1.5229x over previous
#include <cuda_runtime.h>
#include <cuda_bf16.h>
#include <math.h>

#define NN 20000
#define EE 200000
#define ND 64
#define ED 32
#define GD 32
#define HD 128
#define DOF 6
#define PI_F 3.14159265358979f

#define EPB 32     // edges per edge-block
#define RPB 64     // rows per edge-block
#define TPB 256    // edge threads
#define NTPB 512   // node threads

// edge A tiles: pitch 200 els = 400 B (== 16 mod 128 -> ldmatrix conflict-free)
#define SP   200
#define SPB  400
#define EAIMG (RPB * SPB)     // 25600 B per A image
// streamed W chunk: 128 N-rows x 32 K-els, row pitch 80 B
#define ECH_P   80
#define ECH_IMG 10240
#define ECH_ELS 5120
// edge smem layout: [Ah][Al][B0h][B0l][B1h][B1l]
#define EBB   (2 * EAIMG)         // 51200
#define ESMEM (EBB + 4 * ECH_IMG) // 92160 -> 2 blocks/SM

// node tiles: pitch 264 els = 528 B, K up to 224
#define SP2   264
#define SPB2  528
#define NAIMG (64 * SPB2)     // 33792 (A: 64 rows)
#define NBIMG (128 * SPB2)    // 67584 (B: 128 rows)
#define W4ROWS 80
#define NOFF_AH 0
#define NOFF_AL NAIMG
#define NOFF_BH (2 * NAIMG)
#define NOFF_BL (2 * NAIMG + NBIMG)
#define NSMEM   (2 * NAIMG + 2 * NBIMG)   // 202752 -> 1 block/SM

// edge: chunked weight images; node: pitched weight images
static __device__ __align__(16) __nv_bfloat16 gW1ch[6 * ECH_ELS];
static __device__ __align__(16) __nv_bfloat16 gW1cl[6 * ECH_ELS];
static __device__ __align__(16) __nv_bfloat16 gW2ch[4 * ECH_ELS];
static __device__ __align__(16) __nv_bfloat16 gW2cl[4 * ECH_ELS];
static __device__ __align__(16) __nv_bfloat16 gW3h[128 * SP2];
static __device__ __align__(16) __nv_bfloat16 gW3l[128 * SP2];
static __device__ __align__(16) __nv_bfloat16 gW4h[128 * SP2];
static __device__ __align__(16) __nv_bfloat16 gW4l[128 * SP2];

__device__ float g_sums[NN * HD];
__device__ float g_cnt[NN];

__device__ __forceinline__ unsigned smem_u32(const void* p) {
    unsigned a;
    asm("{ .reg .u64 t; cvta.to.shared.u64 t, %1; cvt.u32.u64 %0, t; }" : "=r"(a) : "l"(p));
    return a;
}
__device__ __forceinline__ void split2(float a, float b, unsigned& hi, unsigned& lo) {
    __nv_bfloat16 ha = __float2bfloat16(a), hb = __float2bfloat16(b);
    __nv_bfloat162 th; th.x = ha; th.y = hb;
    hi = *(unsigned*)&th;
    __nv_bfloat162 tl;
    tl.x = __float2bfloat16(a - __bfloat162float(ha));
    tl.y = __float2bfloat16(b - __bfloat162float(hb));
    lo = *(unsigned*)&tl;
}
__device__ __forceinline__ void split4v(float4 v, uint2& hi, uint2& lo) {
    unsigned h0, l0, h1, l1;
    split2(v.x, v.y, h0, l0);
    split2(v.z, v.w, h1, l1);
    hi = make_uint2(h0, h1);
    lo = make_uint2(l0, l1);
}
__device__ __forceinline__ unsigned eoff(int r, int k)  { return (unsigned)(r * SPB  + k * 2); }
__device__ __forceinline__ unsigned eoff2(int r, int k) { return (unsigned)(r * SPB2 + k * 2); }

__device__ __forceinline__ void ldm4(unsigned addr, unsigned* r) {
    asm volatile("ldmatrix.sync.aligned.m8n8.x4.shared.b16 {%0,%1,%2,%3}, [%4];"
        : "=r"(r[0]), "=r"(r[1]), "=r"(r[2]), "=r"(r[3]) : "r"(addr));
}
__device__ __forceinline__ void mma16816(float* d, const unsigned* a, unsigned b0, unsigned b1) {
    asm volatile("mma.sync.aligned.m16n8k16.row.col.f32.bf16.bf16.f32 "
        "{%0,%1,%2,%3}, {%4,%5,%6,%7}, {%8,%9}, {%0,%1,%2,%3};"
        : "+f"(d[0]), "+f"(d[1]), "+f"(d[2]), "+f"(d[3])
        : "r"(a[0]), "r"(a[1]), "r"(a[2]), "r"(a[3]), "r"(b0), "r"(b1));
}

// ---- streamed-chunk helpers (edge kernel) ----
__device__ __forceinline__ void ldg_chunk(const uint2* gh, const uint2* gl, int c, int tid,
                                          uint2 rh[5], uint2 rl[5]) {
    const uint2* ph = gh + c * (ECH_IMG / 8) + tid;
    const uint2* pl = gl + c * (ECH_IMG / 8) + tid;
    #pragma unroll
    for (int i = 0; i < 5; i++) { rh[i] = ph[i * 256]; rl[i] = pl[i * 256]; }
}
__device__ __forceinline__ void sts_chunk(char* bh, char* bl, int tid,
                                          const uint2 rh[5], const uint2 rl[5]) {
    uint2* dh = (uint2*)bh + tid;
    uint2* dl = (uint2*)bl + tid;
    #pragma unroll
    for (int i = 0; i < 5; i++) { dh[i * 256] = rh[i]; dl[i * 256] = rl[i]; }
}

// 3-term MMA over one K32 chunk (warp tile 32x32), edge A pitch
__device__ __forceinline__ void mma_chunk(unsigned aH, unsigned aL, unsigned bH, unsigned bL,
                                          unsigned aoffc, unsigned boff0, int steps,
                                          float d[2][4][4]) {
    for (int s = 0; s < steps; s++) {
        unsigned ka = aoffc + (unsigned)s * 32u;
        unsigned kb = boff0 + (unsigned)s * 32u;
        unsigned ah0[4], ah1[4], al0[4], al1[4];
        unsigned bh0[4], bh1[4], bl0[4], bl1[4];
        ldm4(aH + ka, ah0);
        ldm4(aH + ka + 16u * SPB, ah1);
        ldm4(aL + ka, al0);
        ldm4(aL + ka + 16u * SPB, al1);
        ldm4(bH + kb, bh0);
        ldm4(bH + kb + 16u * ECH_P, bh1);
        ldm4(bL + kb, bl0);
        ldm4(bL + kb + 16u * ECH_P, bl1);
        mma16816(d[0][0], ah0, bh0[0], bh0[1]);
        mma16816(d[0][1], ah0, bh0[2], bh0[3]);
        mma16816(d[0][2], ah0, bh1[0], bh1[1]);
        mma16816(d[0][3], ah0, bh1[2], bh1[3]);
        mma16816(d[1][0], ah1, bh0[0], bh0[1]);
        mma16816(d[1][1], ah1, bh0[2], bh0[3]);
        mma16816(d[1][2], ah1, bh1[0], bh1[1]);
        mma16816(d[1][3], ah1, bh1[2], bh1[3]);
        mma16816(d[0][0], al0, bh0[0], bh0[1]);
        mma16816(d[0][1], al0, bh0[2], bh0[3]);
        mma16816(d[0][2], al0, bh1[0], bh1[1]);
        mma16816(d[0][3], al0, bh1[2], bh1[3]);
        mma16816(d[1][0], al1, bh0[0], bh0[1]);
        mma16816(d[1][1], al1, bh0[2], bh0[3]);
        mma16816(d[1][2], al1, bh1[0], bh1[1]);
        mma16816(d[1][3], al1, bh1[2], bh1[3]);
        mma16816(d[0][0], ah0, bl0[0], bl0[1]);
        mma16816(d[0][1], ah0, bl0[2], bl0[3]);
        mma16816(d[0][2], ah0, bl1[0], bl1[1]);
        mma16816(d[0][3], ah0, bl1[2], bl1[3]);
        mma16816(d[1][0], ah1, bl0[0], bl0[1]);
        mma16816(d[1][1], ah1, bl0[2], bl0[3]);
        mma16816(d[1][2], ah1, bl1[0], bl1[1]);
        mma16816(d[1][3], ah1, bl1[2], bl1[3]);
    }
}

// double-buffered streamed GEMM (edge kernel)
template<int NCH, int LAST>
__device__ __forceinline__ void gemm_stream(const __nv_bfloat16* gWh, const __nv_bfloat16* gWl,
                                            char* smraw, unsigned sb,
                                            unsigned aoff0, unsigned boff0, int tid,
                                            float d[2][4][4]) {
    const uint2* gh = (const uint2*)gWh;
    const uint2* gl = (const uint2*)gWl;
    uint2 rh[5], rl[5];
    ldg_chunk(gh, gl, 0, tid, rh, rl);
    sts_chunk(smraw + EBB, smraw + EBB + ECH_IMG, tid, rh, rl);
    if (NCH > 1) ldg_chunk(gh, gl, 1, tid, rh, rl);
    __syncthreads();
    #pragma unroll
    for (int c = 0; c < NCH; c++) {
        unsigned bH = sb + EBB + (unsigned)((c & 1) ? 2 * ECH_IMG : 0);
        unsigned bL = bH + ECH_IMG;
        int steps = (c == NCH - 1) ? LAST : 2;
        mma_chunk(sb, sb + EAIMG, bH, bL, aoff0 + (unsigned)c * 64u, boff0, steps, d);
        if (c + 1 < NCH)
            sts_chunk(smraw + EBB + (((c + 1) & 1) ? 2 * ECH_IMG : 0),
                      smraw + EBB + (((c + 1) & 1) ? 2 * ECH_IMG : 0) + ECH_IMG, tid, rh, rl);
        if (c + 2 < NCH) ldg_chunk(gh, gl, c + 2, tid, rh, rl);
        __syncthreads();
    }
}

// node-kernel 3-term warp GEMM (32x16 tile)
template<int KSTEPS, int PITCHB>
__device__ __forceinline__ void gemm3n(unsigned aH, unsigned aL, unsigned bH, unsigned bL,
                                       unsigned aoff0, unsigned boff0, float d[2][2][4]) {
    #pragma unroll
    for (int s = 0; s < KSTEPS; s++) {
        unsigned kb = (unsigned)s * 32u;
        unsigned ah0[4], ah1[4], al0[4], al1[4];
        unsigned bh[4], bl[4];
        ldm4(aH + aoff0 + kb, ah0);
        ldm4(aH + aoff0 + 16u * PITCHB + kb, ah1);
        ldm4(aL + aoff0 + kb, al0);
        ldm4(aL + aoff0 + 16u * PITCHB + kb, al1);
        ldm4(bH + boff0 + kb, bh);
        ldm4(bL + boff0 + kb, bl);
        mma16816(d[0][0], ah0, bh[0], bh[1]);
        mma16816(d[0][1], ah0, bh[2], bh[3]);
        mma16816(d[1][0], ah1, bh[0], bh[1]);
        mma16816(d[1][1], ah1, bh[2], bh[3]);
        mma16816(d[0][0], al0, bh[0], bh[1]);
        mma16816(d[0][1], al0, bh[2], bh[3]);
        mma16816(d[1][0], al1, bh[0], bh[1]);
        mma16816(d[1][1], al1, bh[2], bh[3]);
        mma16816(d[0][0], ah0, bl[0], bl[1]);
        mma16816(d[0][1], ah0, bl[2], bl[3]);
        mma16816(d[1][0], ah1, bl[0], bl[1]);
        mma16816(d[1][1], ah1, bl[2], bl[3]);
    }
}

// ---- init: zero accumulators + all weight images (one launch) ----
__global__ void init_kernel(const float* __restrict__ W1, const float* __restrict__ W2,
                            const float* __restrict__ W3, const float* __restrict__ W4) {
    int idx = blockIdx.x * blockDim.x + threadIdx.x;
    if (idx < NN * HD / 4) ((float4*)g_sums)[idx] = make_float4(0.f, 0.f, 0.f, 0.f);
    if (idx < NN)          g_cnt[idx] = 0.0f;

    const int NW1 = 6 * ECH_ELS, NW2 = 4 * ECH_ELS;
    const int NW3 = 128 * 224, NW4 = 128 * 128;
    if (idx < NW1) {
        int c = idx / ECH_ELS, rem = idx % ECH_ELS;
        int n = rem / 40, kk = rem % 40;
        int k = c * 32 + kk;
        float w = (kk < 32 && k < 172) ? W1[k * HD + n] : 0.f;
        __nv_bfloat16 h = __float2bfloat16(w);
        __nv_bfloat16 l = __float2bfloat16(w - __bfloat162float(h));
        gW1ch[idx] = h; gW1cl[idx] = l;
    } else if (idx < NW1 + NW2) {
        int j = idx - NW1;
        int c = j / ECH_ELS, rem = j % ECH_ELS;
        int n = rem / 40, kk = rem % 40;
        int k = c * 32 + kk;
        float w = (kk < 32) ? W2[k * HD + n] : 0.f;
        __nv_bfloat16 h = __float2bfloat16(w);
        __nv_bfloat16 l = __float2bfloat16(w - __bfloat162float(h));
        gW2ch[j] = h; gW2cl[j] = l;
    } else if (idx < NW1 + NW2 + NW3) {
        int j = idx - (NW1 + NW2);
        int n = j / 224, k = j % 224;
        float w = W3[k * HD + n];
        __nv_bfloat16 h = __float2bfloat16(w);
        __nv_bfloat16 l = __float2bfloat16(w - __bfloat162float(h));
        gW3h[n * SP2 + k] = h; gW3l[n * SP2 + k] = l;
    } else if (idx < NW1 + NW2 + NW3 + NW4) {
        int j = idx - (NW1 + NW2 + NW3);
        int n = j / 128, k = j % 128;
        float w = (n < ND + DOF) ? W4[k * (ND + DOF) + n] : 0.f;
        __nv_bfloat16 h = __float2bfloat16(w);
        __nv_bfloat16 l = __float2bfloat16(w - __bfloat162float(h));
        gW4h[n * SP2 + k] = h; gW4l[n * SP2 + k] = l;
    }
}

// ---------------- Edge kernel: 32 edges, streamed W, 2 blocks/SM (R10-proven) ----------------
__global__ __launch_bounds__(TPB, 2)
void edge_kernel(const float* __restrict__ xfeat, const float* __restrict__ T_R,
                 const float* __restrict__ T_t,  const float* __restrict__ edge_feat,
                 const float* __restrict__ TijR, const float* __restrict__ Tijt,
                 const int* __restrict__ ei,
                 const float* __restrict__ b1, const float* __restrict__ b2)
{
    extern __shared__ __align__(16) char smraw[];
    char* sAh = smraw;
    char* sAl = smraw + EAIMG;
    unsigned sb = smem_u32(smraw);

    __shared__ int sNode[RPB];
    __shared__ float sBias1[HD], sBias2[HD];

    int tid = threadIdx.x;
    int warp = tid >> 5, lane = tid & 31;
    int e0 = blockIdx.x * EPB;

    if (tid < HD)          sBias1[tid] = b1[tid];
    else if (tid < 2 * HD) sBias2[tid - HD] = b2[tid - HD];

    {
        int sub = tid & 7;
        int el  = tid >> 3;
        int e   = e0 + el;
        int vi = ei[e], vj = ei[EE + e];
        const float4* xi4 = (const float4*)(xfeat + vi * ND);
        const float4* xj4 = (const float4*)(xfeat + vj * ND);
        const float4* ef4 = (const float4*)(edge_feat + e * ED);
        int rA = el, rB = EPB + el;
        #pragma unroll
        for (int q = sub; q < 16; q += 8) {
            uint2 hi, lo;
            split4v(xi4[q], hi, lo);
            unsigned o1 = eoff(rA, 4 * q), o2 = eoff(rB, 64 + 4 * q);
            *(uint2*)(sAh + o1) = hi; *(uint2*)(sAl + o1) = lo;
            *(uint2*)(sAh + o2) = hi; *(uint2*)(sAl + o2) = lo;
            split4v(xj4[q], hi, lo);
            o1 = eoff(rA, 64 + 4 * q); o2 = eoff(rB, 4 * q);
            *(uint2*)(sAh + o1) = hi; *(uint2*)(sAl + o1) = lo;
            *(uint2*)(sAh + o2) = hi; *(uint2*)(sAl + o2) = lo;
        }
        uint2 hi, lo;
        split4v(ef4[sub], hi, lo);
        unsigned o1 = eoff(rA, 128 + 4 * sub), o2 = eoff(rB, 128 + 4 * sub);
        *(uint2*)(sAh + o1) = hi; *(uint2*)(sAl + o1) = lo;
        *(uint2*)(sAh + o2) = hi; *(uint2*)(sAl + o2) = lo;
    }

    if (tid < EPB) {
        int e = e0 + tid;
        int vi = ei[e], vj = ei[EE + e];
        sNode[tid]       = vj;
        sNode[EPB + tid] = vi;
        float Ri[9], Rj[9], Tr[9], ti[3], tj[3], tt[3];
        #pragma unroll
        for (int k = 0; k < 9; k++) { Ri[k] = T_R[vi*9+k]; Rj[k] = T_R[vj*9+k]; Tr[k] = TijR[e*9+k]; }
        #pragma unroll
        for (int k = 0; k < 3; k++) { ti[k] = T_t[vi*3+k]; tj[k] = T_t[vj*3+k]; tt[k] = Tijt[e*3+k]; }
        float A[9], ta[3];
        #pragma unroll
        for (int r = 0; r < 3; r++)
            #pragma unroll
            for (int c = 0; c < 3; c++)
                A[r*3+c] = Rj[r*3+0]*Ri[c*3+0] + Rj[r*3+1]*Ri[c*3+1] + Rj[r*3+2]*Ri[c*3+2];
        #pragma unroll
        for (int r = 0; r < 3; r++)
            ta[r] = tj[r] - (A[r*3+0]*ti[0] + A[r*3+1]*ti[1] + A[r*3+2]*ti[2]);
        float arrA[12], arrB[12];
        {
            float Re[9], te[3];
            #pragma unroll
            for (int r = 0; r < 3; r++)
                #pragma unroll
                for (int c = 0; c < 3; c++)
                    Re[r*3+c] = A[r*3+0]*Tr[c*3+0] + A[r*3+1]*Tr[c*3+1] + A[r*3+2]*Tr[c*3+2];
            #pragma unroll
            for (int r = 0; r < 3; r++)
                te[r] = ta[r] - (Re[r*3+0]*tt[0] + Re[r*3+1]*tt[1] + Re[r*3+2]*tt[2]);
            arrA[0]=Re[0]; arrA[1]=Re[1]; arrA[2]=Re[2];  arrA[3]=te[0];
            arrA[4]=Re[3]; arrA[5]=Re[4]; arrA[6]=Re[5];  arrA[7]=te[1];
            arrA[8]=Re[6]; arrA[9]=Re[7]; arrA[10]=Re[8]; arrA[11]=te[2];
        }
        {
            float tb[3], Rf[9], tf[3];
            #pragma unroll
            for (int r = 0; r < 3; r++)
                tb[r] = ti[r] - (A[0+r]*tj[0] + A[3+r]*tj[1] + A[6+r]*tj[2]);
            #pragma unroll
            for (int r = 0; r < 3; r++)
                #pragma unroll
                for (int c = 0; c < 3; c++)
                    Rf[r*3+c] = A[0+r]*Tr[0+c] + A[3+r]*Tr[3+c] + A[6+r]*Tr[6+c];
            #pragma unroll
            for (int r = 0; r < 3; r++)
                tf[r] = tb[r] + (A[0+r]*tt[0] + A[3+r]*tt[1] + A[6+r]*tt[2]);
            arrB[0]=Rf[0]; arrB[1]=Rf[1]; arrB[2]=Rf[2];  arrB[3]=tf[0];
            arrB[4]=Rf[3]; arrB[5]=Rf[4]; arrB[6]=Rf[5];  arrB[7]=tf[1];
            arrB[8]=Rf[6]; arrB[9]=Rf[7]; arrB[10]=Rf[8]; arrB[11]=tf[2];
        }
        #pragma unroll
        for (int half = 0; half < 2; half++) {
            int r = half ? (EPB + tid) : tid;
            const float* arr = half ? arrB : arrA;
            #pragma unroll
            for (int m = 0; m < 6; m++) {
                unsigned hi, lo;
                split2(arr[2*m], arr[2*m+1], hi, lo);
                unsigned o = eoff(r, 160 + 2 * m);
                *(unsigned*)(sAh + o) = hi; *(unsigned*)(sAl + o) = lo;
            }
            #pragma unroll
            for (int k = 172; k < 176; k += 2) {
                unsigned o = eoff(r, k);
                *(unsigned*)(sAh + o) = 0u; *(unsigned*)(sAl + o) = 0u;
            }
        }
    }
    // gemm_stream's first __syncthreads orders the build before MMA.

    const int m_base = (warp & 1) * 32;
    const int n_base = (warp >> 1) * 32;
    unsigned aoff0 = (unsigned)((m_base + (lane & 15)) * SPB + (lane >> 4) * 16);
    unsigned boff0 = (unsigned)((n_base + (lane & 7) + ((lane >> 4) & 1) * 8) * ECH_P
                                + ((lane >> 3) & 1) * 16);

    float d[2][4][4];
    #pragma unroll
    for (int i = 0; i < 2; i++)
        #pragma unroll
        for (int j = 0; j < 4; j++)
            #pragma unroll
            for (int c = 0; c < 4; c++) d[i][j][c] = 0.f;

    gemm_stream<6, 1>(gW1ch, gW1cl, smraw, sb, aoff0, boff0, tid, d);

    {
        int r0b = m_base + (lane >> 2);
        int colb = n_base + 2 * (lane & 3);
        #pragma unroll
        for (int mi = 0; mi < 2; mi++) {
            #pragma unroll
            for (int nb = 0; nb < 4; nb++) {
                int col = colb + nb * 8;
                float bx = sBias1[col], by = sBias1[col + 1];
                int r0 = r0b + mi * 16, r1 = r0 + 8;
                unsigned hi, lo;
                split2(fmaxf(d[mi][nb][0] + bx, 0.f), fmaxf(d[mi][nb][1] + by, 0.f), hi, lo);
                unsigned o = eoff(r0, col);
                *(unsigned*)(sAh + o) = hi; *(unsigned*)(sAl + o) = lo;
                split2(fmaxf(d[mi][nb][2] + bx, 0.f), fmaxf(d[mi][nb][3] + by, 0.f), hi, lo);
                o = eoff(r1, col);
                *(unsigned*)(sAh + o) = hi; *(unsigned*)(sAl + o) = lo;
            }
        }
    }
    __syncthreads();

    #pragma unroll
    for (int i = 0; i < 2; i++)
        #pragma unroll
        for (int j = 0; j < 4; j++)
            #pragma unroll
            for (int c = 0; c < 4; c++) d[i][j][c] = 0.f;

    gemm_stream<4, 2>(gW2ch, gW2cl, smraw, sb, aoff0, boff0, tid, d);

    {
        int r0b = m_base + (lane >> 2);
        int colb = n_base + 2 * (lane & 3);
        #pragma unroll
        for (int mi = 0; mi < 2; mi++) {
            int r0 = r0b + mi * 16, r1 = r0 + 8;
            int node0 = sNode[r0], node1 = sNode[r1];
            #pragma unroll
            for (int nb = 0; nb < 4; nb++) {
                int col = colb + nb * 8;
                float bx = sBias2[col], by = sBias2[col + 1];
                float v0 = fmaxf(d[mi][nb][0] + bx, 0.f);
                float v1 = fmaxf(d[mi][nb][1] + by, 0.f);
                float v2 = fmaxf(d[mi][nb][2] + bx, 0.f);
                float v3 = fmaxf(d[mi][nb][3] + by, 0.f);
                float* p0 = g_sums + (size_t)node0 * HD + col;
                float* p1 = g_sums + (size_t)node1 * HD + col;
                asm volatile("red.global.add.v2.f32 [%0], {%1, %2};"
                             :: "l"(p0), "f"(v0), "f"(v1) : "memory");
                asm volatile("red.global.add.v2.f32 [%0], {%1, %2};"
                             :: "l"(p1), "f"(v2), "f"(v3) : "memory");
            }
        }
        if ((warp >> 1) == 0 && (lane & 3) == 0) {
            int rr = lane >> 2;
            atomicAdd(g_cnt + sNode[m_base + rr],      1.0f);
            atomicAdd(g_cnt + sNode[m_base + rr + 8],  1.0f);
            atomicAdd(g_cnt + sNode[m_base + rr + 16], 1.0f);
            atomicAdd(g_cnt + sNode[m_base + rr + 24], 1.0f);
        }
    }
}

// ---------------- Node kernel: R9-proven 512-thread fused 3-term HMMA ----------------
__global__ __launch_bounds__(NTPB, 1)
void node_kernel(const float* __restrict__ xfeat, const float* __restrict__ T_R,
                 const float* __restrict__ T_t,  const float* __restrict__ u,
                 const int* __restrict__ batch,
                 const float* __restrict__ b3, const float* __restrict__ b4,
                 float* __restrict__ out)
{
    extern __shared__ __align__(16) char smraw[];
    char* sAh = smraw + NOFF_AH;
    char* sAl = smraw + NOFF_AL;
    char* sBh = smraw + NOFF_BH;
    char* sBl = smraw + NOFF_BL;
    unsigned sb = smem_u32(smraw);

    __shared__ float sBias3[HD], sBias4[ND + DOF];
    __shared__ float sInv[64];
    __shared__ float sPose[64 * DOF];

    int tid = threadIdx.x;
    int warp = tid >> 5, lane = tid & 31;
    int n0 = blockIdx.x * 64;

    if (tid < HD)                 sBias3[tid] = b3[tid];
    else if (tid < HD + ND + DOF) sBias4[tid - HD] = b4[tid - HD];

    if (tid >= 256 && tid < 320) {
        int r = tid - 256;
        int n = n0 + r;
        sInv[r] = (n < NN) ? 1.0f / fmaxf(g_cnt[n], 1.0f) : 0.f;
    }

    {
        const float4* s1 = (const float4*)gW3h;
        const float4* s2 = (const float4*)gW3l;
        float4* d1 = (float4*)sBh;
        float4* d2 = (float4*)sBl;
        for (int i = tid; i < NBIMG / 16; i += NTPB) { d1[i] = s1[i]; d2[i] = s2[i]; }
    }
    __syncthreads();

    for (int idx = tid; idx < 64 * 112; idx += NTPB) {
        int r = idx / 112;
        int k = 2 * (idx % 112);
        int n = n0 + r;
        float v0 = 0.f, v1 = 0.f;
        if (n < NN) {
            if (k < HD) {
                float iv = sInv[r];
                v0 = g_sums[(size_t)n * HD + k] * iv;
                v1 = g_sums[(size_t)n * HD + k + 1] * iv;
            } else if (k < HD + ND) {
                v0 = xfeat[(size_t)n * ND + k - HD];
                v1 = xfeat[(size_t)n * ND + k - HD + 1];
            } else {
                int bb = batch[n];
                v0 = u[bb * GD + k - HD - ND];
                v1 = u[bb * GD + k - HD - ND + 1];
            }
        }
        unsigned hi, lo;
        split2(v0, v1, hi, lo);
        unsigned o = eoff2(r, k);
        *(unsigned*)(sAh + o) = hi;
        *(unsigned*)(sAl + o) = lo;
    }
    __syncthreads();

    const int m_base = (warp & 1) * 32;
    const int n_base = (warp >> 1) * 16;
    unsigned aoff0 = (unsigned)((m_base + (lane & 15)) * SPB2 + (lane >> 4) * 16);
    unsigned boff0 = (unsigned)((n_base + (lane & 7) + ((lane >> 4) & 1) * 8) * SPB2
                                + ((lane >> 3) & 1) * 16);

    float d[2][2][4];
    #pragma unroll
    for (int i = 0; i < 2; i++)
        #pragma unroll
        for (int j = 0; j < 2; j++)
            #pragma unroll
            for (int c = 0; c < 4; c++) d[i][j][c] = 0.f;

    gemm3n<14, SPB2>(sb + NOFF_AH, sb + NOFF_AL, sb + NOFF_BH, sb + NOFF_BL, aoff0, boff0, d);

    __syncthreads();

    {
        const float4* s1 = (const float4*)gW4h;
        const float4* s2 = (const float4*)gW4l;
        float4* d1 = (float4*)sBh;
        float4* d2 = (float4*)sBl;
        for (int i = tid; i < (W4ROWS * SPB2) / 16; i += NTPB) { d1[i] = s1[i]; d2[i] = s2[i]; }
    }

    {
        int r0b = m_base + (lane >> 2);
        int colb = n_base + 2 * (lane & 3);
        #pragma unroll
        for (int mi = 0; mi < 2; mi++) {
            #pragma unroll
            for (int nb = 0; nb < 2; nb++) {
                int col = colb + nb * 8;
                float bx = sBias3[col], by = sBias3[col + 1];
                int r0 = r0b + mi * 16, r1 = r0 + 8;
                unsigned hi, lo;
                split2(fmaxf(d[mi][nb][0] + bx, 0.f), fmaxf(d[mi][nb][1] + by, 0.f), hi, lo);
                unsigned o = eoff2(r0, col);
                *(unsigned*)(sAh + o) = hi; *(unsigned*)(sAl + o) = lo;
                split2(fmaxf(d[mi][nb][2] + bx, 0.f), fmaxf(d[mi][nb][3] + by, 0.f), hi, lo);
                o = eoff2(r1, col);
                *(unsigned*)(sAh + o) = hi; *(unsigned*)(sAl + o) = lo;
            }
        }
    }
    __syncthreads();

    #pragma unroll
    for (int i = 0; i < 2; i++)
        #pragma unroll
        for (int j = 0; j < 2; j++)
            #pragma unroll
            for (int c = 0; c < 4; c++) d[i][j][c] = 0.f;

    if (n_base < W4ROWS) {
        gemm3n<8, SPB2>(sb + NOFF_AH, sb + NOFF_AL, sb + NOFF_BH, sb + NOFF_BL, aoff0, boff0, d);

        int r0b = m_base + (lane >> 2);
        int colb = n_base + 2 * (lane & 3);
        #pragma unroll
        for (int mi = 0; mi < 2; mi++) {
            #pragma unroll
            for (int rr = 0; rr < 2; rr++) {
                int r = r0b + mi * 16 + rr * 8;
                int n = n0 + r;
                #pragma unroll
                for (int nb = 0; nb < 2; nb++) {
                    int col = colb + nb * 8;
                    float v0 = d[mi][nb][rr * 2 + 0];
                    float v1 = d[mi][nb][rr * 2 + 1];
                    if (col < ND) {
                        if (n < NN) {
                            out[(size_t)n * 77 + col]     = xfeat[(size_t)n * ND + col]     + v0 + sBias4[col];
                            out[(size_t)n * 77 + col + 1] = xfeat[(size_t)n * ND + col + 1] + v1 + sBias4[col + 1];
                        }
                    } else if (col < ND + DOF) {
                        sPose[r * DOF + (col - ND)] = v0 + sBias4[col];
                        if (col + 1 < ND + DOF)
                            sPose[r * DOF + (col - ND) + 1] = v1 + sBias4[col + 1];
                    }
                }
            }
        }
    }
    __syncthreads();

    if (tid < 64) {
        int n = n0 + tid;
        if (n < NN) {
            float r0 = sPose[tid*6+0], r1 = sPose[tid*6+1], r2 = sPose[tid*6+2];
            float px = sPose[tid*6+3], py = sPose[tid*6+4], pz = sPose[tid*6+5];
            float nr = sqrtf(px*px + py*py + pz*pz);
            float sc = PI_F * tanhf(nr / PI_F) / (nr + 1e-8f);
            px *= sc; py *= sc; pz *= sc;
            float pp = px*px + py*py + pz*pz;
            float th = sqrtf(pp + 1e-12f);
            float a, b, c;
            if (th < 1e-4f) {
                a = 1.f - pp/6.f; b = 0.5f - pp/24.f; c = 1.f/6.f - pp/120.f;
            } else {
                float s = sinf(th), co = cosf(th);
                a = s / th; b = (1.f - co) / pp; c = (th - s) / (pp * th);
            }
            float Km[9] = {0.f,-pz,py,  pz,0.f,-px,  -py,px,0.f};
            float KK[9] = {px*px-pp, px*py,    px*pz,
                           py*px,    py*py-pp, py*pz,
                           pz*px,    pz*py,    pz*pz-pp};
            float Rd[9], V[9];
            #pragma unroll
            for (int q = 0; q < 9; q++) { Rd[q] = a*Km[q] + b*KK[q]; V[q] = b*Km[q] + c*KK[q]; }
            Rd[0] += 1.f; Rd[4] += 1.f; Rd[8] += 1.f;
            V[0]  += 1.f; V[4]  += 1.f; V[8]  += 1.f;
            float td0 = V[0]*r0 + V[1]*r1 + V[2]*r2;
            float td1 = V[3]*r0 + V[4]*r1 + V[5]*r2;
            float td2 = V[6]*r0 + V[7]*r1 + V[8]*r2;
            float TR[9], Tt[3];
            #pragma unroll
            for (int q = 0; q < 9; q++) TR[q] = T_R[n*9+q];
            #pragma unroll
            for (int q = 0; q < 3; q++) Tt[q] = T_t[n*3+q];
            float* o = out + (size_t)n * 77;
            #pragma unroll
            for (int rr = 0; rr < 3; rr++) {
                #pragma unroll
                for (int cc = 0; cc < 3; cc++) {
                    o[64 + rr*3 + cc] = Rd[rr*3+0]*TR[0+cc] + Rd[rr*3+1]*TR[3+cc] + Rd[rr*3+2]*TR[6+cc];
                }
                o[73 + rr] = Rd[rr*3+0]*Tt[0] + Rd[rr*3+1]*Tt[1] + Rd[rr*3+2]*Tt[2]
                           + (rr == 0 ? td0 : (rr == 1 ? td1 : td2));
            }
            o[76] = sqrtf(pp);
        }
    }
}

extern "C" void kernel_launch(void* const* d_in, const int* in_sizes, int n_in,
                              void* d_out, int out_size) {
    const float* xfeat     = (const float*)d_in[0];
    const float* T_R       = (const float*)d_in[1];
    const float* T_t       = (const float*)d_in[2];
    const float* edge_feat = (const float*)d_in[3];
    const float* TijR      = (const float*)d_in[4];
    const float* Tijt      = (const float*)d_in[5];
    const float* u         = (const float*)d_in[6];
    const int*   ei        = (const int*)d_in[7];
    const int*   batch     = (const int*)d_in[8];
    const float* W1 = (const float*)d_in[9];
    const float* b1 = (const float*)d_in[10];
    const float* W2 = (const float*)d_in[11];
    const float* b2 = (const float*)d_in[12];
    const float* W3 = (const float*)d_in[13];
    const float* b3 = (const float*)d_in[14];
    const float* W4 = (const float*)d_in[15];
    const float* b4 = (const float*)d_in[16];
    float* out = (float*)d_out;

    cudaFuncSetAttribute(edge_kernel, cudaFuncAttributeMaxDynamicSharedMemorySize, ESMEM);
    cudaFuncSetAttribute(node_kernel, cudaFuncAttributeMaxDynamicSharedMemorySize, NSMEM);

    init_kernel<<<(NN * HD / 4 + 255) / 256, 256>>>(W1, W2, W3, W4);
    edge_kernel<<<EE / EPB, TPB, ESMEM>>>(xfeat, T_R, T_t, edge_feat, TijR, Tijt,
                                          ei, b1, b2);
    node_kernel<<<(NN + 63) / 64, NTPB, NSMEM>>>(xfeat, T_R, T_t, u, batch,
                                                 b3, b4, out);
}

// round 17
// speedup vs baseline: 1.7332x; 1.1381x over previous
#include <cuda_runtime.h>
#include <cuda_bf16.h>
#include <math.h>

#define NN 20000
#define EE 200000
#define ND 64
#define ED 32
#define GD 32
#define HD 128
#define DOF 6
#define PI_F 3.14159265358979f

#define EPB 32     // edges per edge-block
#define RPB 64     // rows per edge-block
#define TPB 256    // edge threads
#define NTPB 512   // node threads

// edge A tiles: pitch 368 B (== 112 mod 128 -> conflict-free, 16B aligned, 184 els >= 176)
#define SPB   368
#define EAIMG (RPB * SPB)         // 23552 B per A image
// streamed W chunk: 128 N-rows x 16 K-els, row pitch 48 B (conflict-free)
#define KCH_P   48
#define KCH_IMG 6144
#define KCH_ELS 3072              // 128 * 24 bf16 slots (16 data + 8 pad)
// edge smem layout: [Ah][Al][B0h][B0l][B1h][B1l]
#define EBB   (2 * EAIMG)         // 47104
#define ESMEM (EBB + 4 * KCH_IMG) // 71680 -> 3 blocks/SM

// node tiles: pitch 264 els = 528 B, K up to 224
#define SP2   264
#define SPB2  528
#define NAIMG (64 * SPB2)     // 33792 (A: 64 rows)
#define NBIMG (128 * SPB2)    // 67584 (B: 128 rows)
#define W4ROWS 80
#define NOFF_AH 0
#define NOFF_AL NAIMG
#define NOFF_BH (2 * NAIMG)
#define NOFF_BL (2 * NAIMG + NBIMG)
#define NSMEM   (2 * NAIMG + 2 * NBIMG)   // 202752 -> 1 block/SM

// edge: K16-chunked weight images; node: pitched weight images
static __device__ __align__(16) __nv_bfloat16 gW1ch[11 * KCH_ELS];
static __device__ __align__(16) __nv_bfloat16 gW1cl[11 * KCH_ELS];
static __device__ __align__(16) __nv_bfloat16 gW2ch[8 * KCH_ELS];
static __device__ __align__(16) __nv_bfloat16 gW2cl[8 * KCH_ELS];
static __device__ __align__(16) __nv_bfloat16 gW3h[128 * SP2];
static __device__ __align__(16) __nv_bfloat16 gW3l[128 * SP2];
static __device__ __align__(16) __nv_bfloat16 gW4h[128 * SP2];
static __device__ __align__(16) __nv_bfloat16 gW4l[128 * SP2];

__device__ float g_sums[NN * HD];
__device__ float g_cnt[NN];

__device__ __forceinline__ unsigned smem_u32(const void* p) {
    unsigned a;
    asm("{ .reg .u64 t; cvta.to.shared.u64 t, %1; cvt.u32.u64 %0, t; }" : "=r"(a) : "l"(p));
    return a;
}
__device__ __forceinline__ void split2(float a, float b, unsigned& hi, unsigned& lo) {
    __nv_bfloat16 ha = __float2bfloat16(a), hb = __float2bfloat16(b);
    __nv_bfloat162 th; th.x = ha; th.y = hb;
    hi = *(unsigned*)&th;
    __nv_bfloat162 tl;
    tl.x = __float2bfloat16(a - __bfloat162float(ha));
    tl.y = __float2bfloat16(b - __bfloat162float(hb));
    lo = *(unsigned*)&tl;
}
__device__ __forceinline__ void split4v(float4 v, uint2& hi, uint2& lo) {
    unsigned h0, l0, h1, l1;
    split2(v.x, v.y, h0, l0);
    split2(v.z, v.w, h1, l1);
    hi = make_uint2(h0, h1);
    lo = make_uint2(l0, l1);
}
__device__ __forceinline__ unsigned eoff(int r, int k)  { return (unsigned)(r * SPB  + k * 2); }
__device__ __forceinline__ unsigned eoff2(int r, int k) { return (unsigned)(r * SPB2 + k * 2); }

__device__ __forceinline__ void ldm4(unsigned addr, unsigned* r) {
    asm volatile("ldmatrix.sync.aligned.m8n8.x4.shared.b16 {%0,%1,%2,%3}, [%4];"
        : "=r"(r[0]), "=r"(r[1]), "=r"(r[2]), "=r"(r[3]) : "r"(addr));
}
__device__ __forceinline__ void mma16816(float* d, const unsigned* a, unsigned b0, unsigned b1) {
    asm volatile("mma.sync.aligned.m16n8k16.row.col.f32.bf16.bf16.f32 "
        "{%0,%1,%2,%3}, {%4,%5,%6,%7}, {%8,%9}, {%0,%1,%2,%3};"
        : "+f"(d[0]), "+f"(d[1]), "+f"(d[2]), "+f"(d[3])
        : "r"(a[0]), "r"(a[1]), "r"(a[2]), "r"(a[3]), "r"(b0), "r"(b1));
}
__device__ __forceinline__ void cpa16(unsigned dst, const void* src) {
    asm volatile("cp.async.cg.shared.global [%0], [%1], 16;" :: "r"(dst), "l"(src) : "memory");
}
#define CPA_COMMIT() asm volatile("cp.async.commit_group;" ::: "memory")

// issue async copy of chunk c into (bufH, bufL); 768 x 16B ops over 256 threads
__device__ __forceinline__ void cpa_chunk(const __nv_bfloat16* gWh, const __nv_bfloat16* gWl,
                                          int c, unsigned bufH, unsigned bufL, int tid) {
    const char* sh = (const char*)gWh + (size_t)c * KCH_IMG;
    const char* sl = (const char*)gWl + (size_t)c * KCH_IMG;
    #pragma unroll
    for (int i = 0; i < 3; i++) {
        int o = tid + i * 256;
        if (o < 384) cpa16(bufH + o * 16, sh + o * 16);
        else         cpa16(bufL + (o - 384) * 16, sl + (o - 384) * 16);
    }
    CPA_COMMIT();
}

// 3-term MMA over one K16 chunk (warp tile 32x32)
__device__ __forceinline__ void mma_chunk16(unsigned aH, unsigned aL, unsigned bH, unsigned bL,
                                            unsigned aoffc, unsigned boff0, float d[2][4][4]) {
    unsigned ah0[4], ah1[4], al0[4], al1[4];
    unsigned bh0[4], bh1[4], bl0[4], bl1[4];
    ldm4(aH + aoffc, ah0);
    ldm4(aH + aoffc + 16u * SPB, ah1);
    ldm4(aL + aoffc, al0);
    ldm4(aL + aoffc + 16u * SPB, al1);
    ldm4(bH + boff0, bh0);
    ldm4(bH + boff0 + 16u * KCH_P, bh1);
    ldm4(bL + boff0, bl0);
    ldm4(bL + boff0 + 16u * KCH_P, bl1);
    mma16816(d[0][0], ah0, bh0[0], bh0[1]);
    mma16816(d[0][1], ah0, bh0[2], bh0[3]);
    mma16816(d[0][2], ah0, bh1[0], bh1[1]);
    mma16816(d[0][3], ah0, bh1[2], bh1[3]);
    mma16816(d[1][0], ah1, bh0[0], bh0[1]);
    mma16816(d[1][1], ah1, bh0[2], bh0[3]);
    mma16816(d[1][2], ah1, bh1[0], bh1[1]);
    mma16816(d[1][3], ah1, bh1[2], bh1[3]);
    mma16816(d[0][0], al0, bh0[0], bh0[1]);
    mma16816(d[0][1], al0, bh0[2], bh0[3]);
    mma16816(d[0][2], al0, bh1[0], bh1[1]);
    mma16816(d[0][3], al0, bh1[2], bh1[3]);
    mma16816(d[1][0], al1, bh0[0], bh0[1]);
    mma16816(d[1][1], al1, bh0[2], bh0[3]);
    mma16816(d[1][2], al1, bh1[0], bh1[1]);
    mma16816(d[1][3], al1, bh1[2], bh1[3]);
    mma16816(d[0][0], ah0, bl0[0], bl0[1]);
    mma16816(d[0][1], ah0, bl0[2], bl0[3]);
    mma16816(d[0][2], ah0, bl1[0], bl1[1]);
    mma16816(d[0][3], ah0, bl1[2], bl1[3]);
    mma16816(d[1][0], ah1, bl0[0], bl0[1]);
    mma16816(d[1][1], ah1, bl0[2], bl0[3]);
    mma16816(d[1][2], ah1, bl1[0], bl1[1]);
    mma16816(d[1][3], ah1, bl1[2], bl1[3]);
}

// cp.async double-buffered streamed GEMM over NCH K16 chunks
template<int NCH>
__device__ __forceinline__ void gemm_streamA(const __nv_bfloat16* gWh, const __nv_bfloat16* gWl,
                                             unsigned sb, unsigned aoff0, unsigned boff0,
                                             int tid, float d[2][4][4]) {
    unsigned b0H = sb + EBB,          b0L = b0H + KCH_IMG;
    unsigned b1H = b0L + KCH_IMG,     b1L = b1H + KCH_IMG;
    cpa_chunk(gWh, gWl, 0, b0H, b0L, tid);
    cpa_chunk(gWh, gWl, 1, b1H, b1L, tid);
    #pragma unroll
    for (int c = 0; c < NCH; c++) {
        if (c + 1 < NCH) asm volatile("cp.async.wait_group 1;" ::: "memory");
        else             asm volatile("cp.async.wait_group 0;" ::: "memory");
        __syncthreads();                  // chunk c visible to all (also orders build at c=0)
        unsigned bH = (c & 1) ? b1H : b0H;
        unsigned bL = (c & 1) ? b1L : b0L;
        mma_chunk16(sb, sb + EAIMG, bH, bL, aoff0 + (unsigned)c * 32u, boff0, d);
        __syncthreads();                  // all warps done reading buf (c&1)
        if (c + 2 < NCH) cpa_chunk(gWh, gWl, c + 2, bH, bL, tid);
    }
}

// node-kernel 3-term warp GEMM (32x16 tile)
template<int KSTEPS, int PITCHB>
__device__ __forceinline__ void gemm3n(unsigned aH, unsigned aL, unsigned bH, unsigned bL,
                                       unsigned aoff0, unsigned boff0, float d[2][2][4]) {
    #pragma unroll
    for (int s = 0; s < KSTEPS; s++) {
        unsigned kb = (unsigned)s * 32u;
        unsigned ah0[4], ah1[4], al0[4], al1[4];
        unsigned bh[4], bl[4];
        ldm4(aH + aoff0 + kb, ah0);
        ldm4(aH + aoff0 + 16u * PITCHB + kb, ah1);
        ldm4(aL + aoff0 + kb, al0);
        ldm4(aL + aoff0 + 16u * PITCHB + kb, al1);
        ldm4(bH + boff0 + kb, bh);
        ldm4(bL + boff0 + kb, bl);
        mma16816(d[0][0], ah0, bh[0], bh[1]);
        mma16816(d[0][1], ah0, bh[2], bh[3]);
        mma16816(d[1][0], ah1, bh[0], bh[1]);
        mma16816(d[1][1], ah1, bh[2], bh[3]);
        mma16816(d[0][0], al0, bh[0], bh[1]);
        mma16816(d[0][1], al0, bh[2], bh[3]);
        mma16816(d[1][0], al1, bh[0], bh[1]);
        mma16816(d[1][1], al1, bh[2], bh[3]);
        mma16816(d[0][0], ah0, bl[0], bl[1]);
        mma16816(d[0][1], ah0, bl[2], bl[3]);
        mma16816(d[1][0], ah1, bl[0], bl[1]);
        mma16816(d[1][1], ah1, bl[2], bl[3]);
    }
}

// ---- init: zero accumulators + all weight images (one launch) ----
__global__ void init_kernel(const float* __restrict__ W1, const float* __restrict__ W2,
                            const float* __restrict__ W3, const float* __restrict__ W4) {
    int idx = blockIdx.x * blockDim.x + threadIdx.x;
    if (idx < NN * HD / 4) ((float4*)g_sums)[idx] = make_float4(0.f, 0.f, 0.f, 0.f);
    if (idx < NN)          g_cnt[idx] = 0.0f;

    const int NW1 = 11 * KCH_ELS, NW2 = 8 * KCH_ELS;
    const int NW3 = 128 * 224, NW4 = 128 * 128;
    if (idx < NW1) {
        int c = idx / KCH_ELS, rem = idx % KCH_ELS;
        int n = rem / 24, kk = rem % 24;
        int k = c * 16 + kk;
        float w = (kk < 16 && k < 172) ? W1[k * HD + n] : 0.f;
        __nv_bfloat16 h = __float2bfloat16(w);
        __nv_bfloat16 l = __float2bfloat16(w - __bfloat162float(h));
        gW1ch[idx] = h; gW1cl[idx] = l;
    } else if (idx < NW1 + NW2) {
        int j = idx - NW1;
        int c = j / KCH_ELS, rem = j % KCH_ELS;
        int n = rem / 24, kk = rem % 24;
        int k = c * 16 + kk;
        float w = (kk < 16) ? W2[k * HD + n] : 0.f;
        __nv_bfloat16 h = __float2bfloat16(w);
        __nv_bfloat16 l = __float2bfloat16(w - __bfloat162float(h));
        gW2ch[j] = h; gW2cl[j] = l;
    } else if (idx < NW1 + NW2 + NW3) {
        int j = idx - (NW1 + NW2);
        int n = j / 224, k = j % 224;
        float w = W3[k * HD + n];
        __nv_bfloat16 h = __float2bfloat16(w);
        __nv_bfloat16 l = __float2bfloat16(w - __bfloat162float(h));
        gW3h[n * SP2 + k] = h; gW3l[n * SP2 + k] = l;
    } else if (idx < NW1 + NW2 + NW3 + NW4) {
        int j = idx - (NW1 + NW2 + NW3);
        int n = j / 128, k = j % 128;
        float w = (n < ND + DOF) ? W4[k * (ND + DOF) + n] : 0.f;
        __nv_bfloat16 h = __float2bfloat16(w);
        __nv_bfloat16 l = __float2bfloat16(w - __bfloat162float(h));
        gW4h[n * SP2 + k] = h; gW4l[n * SP2 + k] = l;
    }
}

// ---------------- Edge kernel: 32 edges, cp.async K16 stream, 3 blocks/SM ----------------
__global__ __launch_bounds__(TPB, 3)
void edge_kernel(const float* __restrict__ xfeat, const float* __restrict__ T_R,
                 const float* __restrict__ T_t,  const float* __restrict__ edge_feat,
                 const float* __restrict__ TijR, const float* __restrict__ Tijt,
                 const int* __restrict__ ei,
                 const float* __restrict__ b1, const float* __restrict__ b2)
{
    extern __shared__ __align__(16) char smraw[];
    char* sAh = smraw;
    char* sAl = smraw + EAIMG;
    unsigned sb = smem_u32(smraw);

    __shared__ int sNode[RPB];
    __shared__ float sBias1[HD], sBias2[HD];

    int tid = threadIdx.x;
    int warp = tid >> 5, lane = tid & 31;
    int e0 = blockIdx.x * EPB;

    if (tid < HD)          sBias1[tid] = b1[tid];
    else if (tid < 2 * HD) sBias2[tid - HD] = b2[tid - HD];

    {
        int sub = tid & 7;
        int el  = tid >> 3;
        int e   = e0 + el;
        int vi = ei[e], vj = ei[EE + e];
        const float4* xi4 = (const float4*)(xfeat + vi * ND);
        const float4* xj4 = (const float4*)(xfeat + vj * ND);
        const float4* ef4 = (const float4*)(edge_feat + e * ED);
        int rA = el, rB = EPB + el;
        #pragma unroll
        for (int q = sub; q < 16; q += 8) {
            uint2 hi, lo;
            split4v(xi4[q], hi, lo);
            unsigned o1 = eoff(rA, 4 * q), o2 = eoff(rB, 64 + 4 * q);
            *(uint2*)(sAh + o1) = hi; *(uint2*)(sAl + o1) = lo;
            *(uint2*)(sAh + o2) = hi; *(uint2*)(sAl + o2) = lo;
            split4v(xj4[q], hi, lo);
            o1 = eoff(rA, 64 + 4 * q); o2 = eoff(rB, 4 * q);
            *(uint2*)(sAh + o1) = hi; *(uint2*)(sAl + o1) = lo;
            *(uint2*)(sAh + o2) = hi; *(uint2*)(sAl + o2) = lo;
        }
        uint2 hi, lo;
        split4v(ef4[sub], hi, lo);
        unsigned o1 = eoff(rA, 128 + 4 * sub), o2 = eoff(rB, 128 + 4 * sub);
        *(uint2*)(sAh + o1) = hi; *(uint2*)(sAl + o1) = lo;
        *(uint2*)(sAh + o2) = hi; *(uint2*)(sAl + o2) = lo;
    }

    if (tid < EPB) {
        int e = e0 + tid;
        int vi = ei[e], vj = ei[EE + e];
        sNode[tid]       = vj;
        sNode[EPB + tid] = vi;
        float Ri[9], Rj[9], Tr[9], ti[3], tj[3], tt[3];
        #pragma unroll
        for (int k = 0; k < 9; k++) { Ri[k] = T_R[vi*9+k]; Rj[k] = T_R[vj*9+k]; Tr[k] = TijR[e*9+k]; }
        #pragma unroll
        for (int k = 0; k < 3; k++) { ti[k] = T_t[vi*3+k]; tj[k] = T_t[vj*3+k]; tt[k] = Tijt[e*3+k]; }
        float A[9], ta[3];
        #pragma unroll
        for (int r = 0; r < 3; r++)
            #pragma unroll
            for (int c = 0; c < 3; c++)
                A[r*3+c] = Rj[r*3+0]*Ri[c*3+0] + Rj[r*3+1]*Ri[c*3+1] + Rj[r*3+2]*Ri[c*3+2];
        #pragma unroll
        for (int r = 0; r < 3; r++)
            ta[r] = tj[r] - (A[r*3+0]*ti[0] + A[r*3+1]*ti[1] + A[r*3+2]*ti[2]);
        float arrA[12], arrB[12];
        {
            float Re[9], te[3];
            #pragma unroll
            for (int r = 0; r < 3; r++)
                #pragma unroll
                for (int c = 0; c < 3; c++)
                    Re[r*3+c] = A[r*3+0]*Tr[c*3+0] + A[r*3+1]*Tr[c*3+1] + A[r*3+2]*Tr[c*3+2];
            #pragma unroll
            for (int r = 0; r < 3; r++)
                te[r] = ta[r] - (Re[r*3+0]*tt[0] + Re[r*3+1]*tt[1] + Re[r*3+2]*tt[2]);
            arrA[0]=Re[0]; arrA[1]=Re[1]; arrA[2]=Re[2];  arrA[3]=te[0];
            arrA[4]=Re[3]; arrA[5]=Re[4]; arrA[6]=Re[5];  arrA[7]=te[1];
            arrA[8]=Re[6]; arrA[9]=Re[7]; arrA[10]=Re[8]; arrA[11]=te[2];
        }
        {
            float tb[3], Rf[9], tf[3];
            #pragma unroll
            for (int r = 0; r < 3; r++)
                tb[r] = ti[r] - (A[0+r]*tj[0] + A[3+r]*tj[1] + A[6+r]*tj[2]);
            #pragma unroll
            for (int r = 0; r < 3; r++)
                #pragma unroll
                for (int c = 0; c < 3; c++)
                    Rf[r*3+c] = A[0+r]*Tr[0+c] + A[3+r]*Tr[3+c] + A[6+r]*Tr[6+c];
            #pragma unroll
            for (int r = 0; r < 3; r++)
                tf[r] = tb[r] + (A[0+r]*tt[0] + A[3+r]*tt[1] + A[6+r]*tt[2]);
            arrB[0]=Rf[0]; arrB[1]=Rf[1]; arrB[2]=Rf[2];  arrB[3]=tf[0];
            arrB[4]=Rf[3]; arrB[5]=Rf[4]; arrB[6]=Rf[5];  arrB[7]=tf[1];
            arrB[8]=Rf[6]; arrB[9]=Rf[7]; arrB[10]=Rf[8]; arrB[11]=tf[2];
        }
        #pragma unroll
        for (int half = 0; half < 2; half++) {
            int r = half ? (EPB + tid) : tid;
            const float* arr = half ? arrB : arrA;
            #pragma unroll
            for (int m = 0; m < 6; m++) {
                unsigned hi, lo;
                split2(arr[2*m], arr[2*m+1], hi, lo);
                unsigned o = eoff(r, 160 + 2 * m);
                *(unsigned*)(sAh + o) = hi; *(unsigned*)(sAl + o) = lo;
            }
            #pragma unroll
            for (int k = 172; k < 176; k += 2) {
                unsigned o = eoff(r, k);
                *(unsigned*)(sAh + o) = 0u; *(unsigned*)(sAl + o) = 0u;
            }
        }
    }
    // gemm_streamA's first __syncthreads orders the build before MMA.

    const int m_base = (warp & 1) * 32;
    const int n_base = (warp >> 1) * 32;
    unsigned aoff0 = (unsigned)((m_base + (lane & 15)) * SPB + (lane >> 4) * 16);
    unsigned boff0 = (unsigned)((n_base + (lane & 7) + ((lane >> 4) & 1) * 8) * KCH_P
                                + ((lane >> 3) & 1) * 16);

    float d[2][4][4];
    #pragma unroll
    for (int i = 0; i < 2; i++)
        #pragma unroll
        for (int j = 0; j < 4; j++)
            #pragma unroll
            for (int c = 0; c < 4; c++) d[i][j][c] = 0.f;

    // GEMM1: K=176 = 11 K16 chunks
    gemm_streamA<11>(gW1ch, gW1cl, sb, aoff0, boff0, tid, d);

    {
        int r0b = m_base + (lane >> 2);
        int colb = n_base + 2 * (lane & 3);
        #pragma unroll
        for (int mi = 0; mi < 2; mi++) {
            #pragma unroll
            for (int nb = 0; nb < 4; nb++) {
                int col = colb + nb * 8;
                float bx = sBias1[col], by = sBias1[col + 1];
                int r0 = r0b + mi * 16, r1 = r0 + 8;
                unsigned hi, lo;
                split2(fmaxf(d[mi][nb][0] + bx, 0.f), fmaxf(d[mi][nb][1] + by, 0.f), hi, lo);
                unsigned o = eoff(r0, col);
                *(unsigned*)(sAh + o) = hi; *(unsigned*)(sAl + o) = lo;
                split2(fmaxf(d[mi][nb][2] + bx, 0.f), fmaxf(d[mi][nb][3] + by, 0.f), hi, lo);
                o = eoff(r1, col);
                *(unsigned*)(sAh + o) = hi; *(unsigned*)(sAl + o) = lo;
            }
        }
    }
    __syncthreads();   // H tile complete before GEMM2 reads it

    #pragma unroll
    for (int i = 0; i < 2; i++)
        #pragma unroll
        for (int j = 0; j < 4; j++)
            #pragma unroll
            for (int c = 0; c < 4; c++) d[i][j][c] = 0.f;

    // GEMM2: K=128 = 8 K16 chunks
    gemm_streamA<8>(gW2ch, gW2cl, sb, aoff0, boff0, tid, d);

    {
        int r0b = m_base + (lane >> 2);
        int colb = n_base + 2 * (lane & 3);
        #pragma unroll
        for (int mi = 0; mi < 2; mi++) {
            int r0 = r0b + mi * 16, r1 = r0 + 8;
            int node0 = sNode[r0], node1 = sNode[r1];
            #pragma unroll
            for (int nb = 0; nb < 4; nb++) {
                int col = colb + nb * 8;
                float bx = sBias2[col], by = sBias2[col + 1];
                float v0 = fmaxf(d[mi][nb][0] + bx, 0.f);
                float v1 = fmaxf(d[mi][nb][1] + by, 0.f);
                float v2 = fmaxf(d[mi][nb][2] + bx, 0.f);
                float v3 = fmaxf(d[mi][nb][3] + by, 0.f);
                float* p0 = g_sums + (size_t)node0 * HD + col;
                float* p1 = g_sums + (size_t)node1 * HD + col;
                asm volatile("red.global.add.v2.f32 [%0], {%1, %2};"
                             :: "l"(p0), "f"(v0), "f"(v1) : "memory");
                asm volatile("red.global.add.v2.f32 [%0], {%1, %2};"
                             :: "l"(p1), "f"(v2), "f"(v3) : "memory");
            }
        }
        if ((warp >> 1) == 0 && (lane & 3) == 0) {
            int rr = lane >> 2;
            atomicAdd(g_cnt + sNode[m_base + rr],      1.0f);
            atomicAdd(g_cnt + sNode[m_base + rr + 8],  1.0f);
            atomicAdd(g_cnt + sNode[m_base + rr + 16], 1.0f);
            atomicAdd(g_cnt + sNode[m_base + rr + 24], 1.0f);
        }
    }
}

// ---------------- Node kernel: R9-proven 512-thread fused 3-term HMMA ----------------
__global__ __launch_bounds__(NTPB, 1)
void node_kernel(const float* __restrict__ xfeat, const float* __restrict__ T_R,
                 const float* __restrict__ T_t,  const float* __restrict__ u,
                 const int* __restrict__ batch,
                 const float* __restrict__ b3, const float* __restrict__ b4,
                 float* __restrict__ out)
{
    extern __shared__ __align__(16) char smraw[];
    char* sAh = smraw + NOFF_AH;
    char* sAl = smraw + NOFF_AL;
    char* sBh = smraw + NOFF_BH;
    char* sBl = smraw + NOFF_BL;
    unsigned sb = smem_u32(smraw);

    __shared__ float sBias3[HD], sBias4[ND + DOF];
    __shared__ float sInv[64];
    __shared__ float sPose[64 * DOF];

    int tid = threadIdx.x;
    int warp = tid >> 5, lane = tid & 31;
    int n0 = blockIdx.x * 64;

    if (tid < HD)                 sBias3[tid] = b3[tid];
    else if (tid < HD + ND + DOF) sBias4[tid - HD] = b4[tid - HD];

    if (tid >= 256 && tid < 320) {
        int r = tid - 256;
        int n = n0 + r;
        sInv[r] = (n < NN) ? 1.0f / fmaxf(g_cnt[n], 1.0f) : 0.f;
    }

    {
        const float4* s1 = (const float4*)gW3h;
        const float4* s2 = (const float4*)gW3l;
        float4* d1 = (float4*)sBh;
        float4* d2 = (float4*)sBl;
        for (int i = tid; i < NBIMG / 16; i += NTPB) { d1[i] = s1[i]; d2[i] = s2[i]; }
    }
    __syncthreads();

    for (int idx = tid; idx < 64 * 112; idx += NTPB) {
        int r = idx / 112;
        int k = 2 * (idx % 112);
        int n = n0 + r;
        float v0 = 0.f, v1 = 0.f;
        if (n < NN) {
            if (k < HD) {
                float iv = sInv[r];
                v0 = g_sums[(size_t)n * HD + k] * iv;
                v1 = g_sums[(size_t)n * HD + k + 1] * iv;
            } else if (k < HD + ND) {
                v0 = xfeat[(size_t)n * ND + k - HD];
                v1 = xfeat[(size_t)n * ND + k - HD + 1];
            } else {
                int bb = batch[n];
                v0 = u[bb * GD + k - HD - ND];
                v1 = u[bb * GD + k - HD - ND + 1];
            }
        }
        unsigned hi, lo;
        split2(v0, v1, hi, lo);
        unsigned o = eoff2(r, k);
        *(unsigned*)(sAh + o) = hi;
        *(unsigned*)(sAl + o) = lo;
    }
    __syncthreads();

    const int m_base = (warp & 1) * 32;
    const int n_base = (warp >> 1) * 16;
    unsigned aoff0 = (unsigned)((m_base + (lane & 15)) * SPB2 + (lane >> 4) * 16);
    unsigned boff0 = (unsigned)((n_base + (lane & 7) + ((lane >> 4) & 1) * 8) * SPB2
                                + ((lane >> 3) & 1) * 16);

    float d[2][2][4];
    #pragma unroll
    for (int i = 0; i < 2; i++)
        #pragma unroll
        for (int j = 0; j < 2; j++)
            #pragma unroll
            for (int c = 0; c < 4; c++) d[i][j][c] = 0.f;

    gemm3n<14, SPB2>(sb + NOFF_AH, sb + NOFF_AL, sb + NOFF_BH, sb + NOFF_BL, aoff0, boff0, d);

    __syncthreads();

    {
        const float4* s1 = (const float4*)gW4h;
        const float4* s2 = (const float4*)gW4l;
        float4* d1 = (float4*)sBh;
        float4* d2 = (float4*)sBl;
        for (int i = tid; i < (W4ROWS * SPB2) / 16; i += NTPB) { d1[i] = s1[i]; d2[i] = s2[i]; }
    }

    {
        int r0b = m_base + (lane >> 2);
        int colb = n_base + 2 * (lane & 3);
        #pragma unroll
        for (int mi = 0; mi < 2; mi++) {
            #pragma unroll
            for (int nb = 0; nb < 2; nb++) {
                int col = colb + nb * 8;
                float bx = sBias3[col], by = sBias3[col + 1];
                int r0 = r0b + mi * 16, r1 = r0 + 8;
                unsigned hi, lo;
                split2(fmaxf(d[mi][nb][0] + bx, 0.f), fmaxf(d[mi][nb][1] + by, 0.f), hi, lo);
                unsigned o = eoff2(r0, col);
                *(unsigned*)(sAh + o) = hi; *(unsigned*)(sAl + o) = lo;
                split2(fmaxf(d[mi][nb][2] + bx, 0.f), fmaxf(d[mi][nb][3] + by, 0.f), hi, lo);
                o = eoff2(r1, col);
                *(unsigned*)(sAh + o) = hi; *(unsigned*)(sAl + o) = lo;
            }
        }
    }
    __syncthreads();

    #pragma unroll
    for (int i = 0; i < 2; i++)
        #pragma unroll
        for (int j = 0; j < 2; j++)
            #pragma unroll
            for (int c = 0; c < 4; c++) d[i][j][c] = 0.f;

    if (n_base < W4ROWS) {
        gemm3n<8, SPB2>(sb + NOFF_AH, sb + NOFF_AL, sb + NOFF_BH, sb + NOFF_BL, aoff0, boff0, d);

        int r0b = m_base + (lane >> 2);
        int colb = n_base + 2 * (lane & 3);
        #pragma unroll
        for (int mi = 0; mi < 2; mi++) {
            #pragma unroll
            for (int rr = 0; rr < 2; rr++) {
                int r = r0b + mi * 16 + rr * 8;
                int n = n0 + r;
                #pragma unroll
                for (int nb = 0; nb < 2; nb++) {
                    int col = colb + nb * 8;
                    float v0 = d[mi][nb][rr * 2 + 0];
                    float v1 = d[mi][nb][rr * 2 + 1];
                    if (col < ND) {
                        if (n < NN) {
                            out[(size_t)n * 77 + col]     = xfeat[(size_t)n * ND + col]     + v0 + sBias4[col];
                            out[(size_t)n * 77 + col + 1] = xfeat[(size_t)n * ND + col + 1] + v1 + sBias4[col + 1];
                        }
                    } else if (col < ND + DOF) {
                        sPose[r * DOF + (col - ND)] = v0 + sBias4[col];
                        if (col + 1 < ND + DOF)
                            sPose[r * DOF + (col - ND) + 1] = v1 + sBias4[col + 1];
                    }
                }
            }
        }
    }
    __syncthreads();

    if (tid < 64) {
        int n = n0 + tid;
        if (n < NN) {
            float r0 = sPose[tid*6+0], r1 = sPose[tid*6+1], r2 = sPose[tid*6+2];
            float px = sPose[tid*6+3], py = sPose[tid*6+4], pz = sPose[tid*6+5];
            float nr = sqrtf(px*px + py*py + pz*pz);
            float sc = PI_F * tanhf(nr / PI_F) / (nr + 1e-8f);
            px *= sc; py *= sc; pz *= sc;
            float pp = px*px + py*py + pz*pz;
            float th = sqrtf(pp + 1e-12f);
            float a, b, c;
            if (th < 1e-4f) {
                a = 1.f - pp/6.f; b = 0.5f - pp/24.f; c = 1.f/6.f - pp/120.f;
            } else {
                float s = sinf(th), co = cosf(th);
                a = s / th; b = (1.f - co) / pp; c = (th - s) / (pp * th);
            }
            float Km[9] = {0.f,-pz,py,  pz,0.f,-px,  -py,px,0.f};
            float KK[9] = {px*px-pp, px*py,    px*pz,
                           py*px,    py*py-pp, py*pz,
                           pz*px,    pz*py,    pz*pz-pp};
            float Rd[9], V[9];
            #pragma unroll
            for (int q = 0; q < 9; q++) { Rd[q] = a*Km[q] + b*KK[q]; V[q] = b*Km[q] + c*KK[q]; }
            Rd[0] += 1.f; Rd[4] += 1.f; Rd[8] += 1.f;
            V[0]  += 1.f; V[4]  += 1.f; V[8]  += 1.f;
            float td0 = V[0]*r0 + V[1]*r1 + V[2]*r2;
            float td1 = V[3]*r0 + V[4]*r1 + V[5]*r2;
            float td2 = V[6]*r0 + V[7]*r1 + V[8]*r2;
            float TR[9], Tt[3];
            #pragma unroll
            for (int q = 0; q < 9; q++) TR[q] = T_R[n*9+q];
            #pragma unroll
            for (int q = 0; q < 3; q++) Tt[q] = T_t[n*3+q];
            float* o = out + (size_t)n * 77;
            #pragma unroll
            for (int rr = 0; rr < 3; rr++) {
                #pragma unroll
                for (int cc = 0; cc < 3; cc++) {
                    o[64 + rr*3 + cc] = Rd[rr*3+0]*TR[0+cc] + Rd[rr*3+1]*TR[3+cc] + Rd[rr*3+2]*TR[6+cc];
                }
                o[73 + rr] = Rd[rr*3+0]*Tt[0] + Rd[rr*3+1]*Tt[1] + Rd[rr*3+2]*Tt[2]
                           + (rr == 0 ? td0 : (rr == 1 ? td1 : td2));
            }
            o[76] = sqrtf(pp);
        }
    }
}

extern "C" void kernel_launch(void* const* d_in, const int* in_sizes, int n_in,
                              void* d_out, int out_size) {
    const float* xfeat     = (const float*)d_in[0];
    const float* T_R       = (const float*)d_in[1];
    const float* T_t       = (const float*)d_in[2];
    const float* edge_feat = (const float*)d_in[3];
    const float* TijR      = (const float*)d_in[4];
    const float* Tijt      = (const float*)d_in[5];
    const float* u         = (const float*)d_in[6];
    const int*   ei        = (const int*)d_in[7];
    const int*   batch     = (const int*)d_in[8];
    const float* W1 = (const float*)d_in[9];
    const float* b1 = (const float*)d_in[10];
    const float* W2 = (const float*)d_in[11];
    const float* b2 = (const float*)d_in[12];
    const float* W3 = (const float*)d_in[13];
    const float* b3 = (const float*)d_in[14];
    const float* W4 = (const float*)d_in[15];
    const float* b4 = (const float*)d_in[16];
    float* out = (float*)d_out;

    cudaFuncSetAttribute(edge_kernel, cudaFuncAttributeMaxDynamicSharedMemorySize, ESMEM);
    cudaFuncSetAttribute(node_kernel, cudaFuncAttributeMaxDynamicSharedMemorySize, NSMEM);

    init_kernel<<<(NN * HD / 4 + 255) / 256, 256>>>(W1, W2, W3, W4);
    edge_kernel<<<EE / EPB, TPB, ESMEM>>>(xfeat, T_R, T_t, edge_feat, TijR, Tijt,
                                          ei, b1, b2);
    node_kernel<<<(NN + 63) / 64, NTPB, NSMEM>>>(xfeat, T_R, T_t, u, batch,
                                                 b3, b4, out);
}